// round 1
// baseline (speedup 1.0000x reference)
#include <cuda_runtime.h>
#include <cuda_bf16.h>
#include <math.h>

// ---------------------------------------------------------------------------
// GCN: 3x { H = A_sparse @ (H @ W) + b (,ReLU) } -> log_softmax
// Shapes: N=50000 nodes, E=1.6M edges, 512 -> 128 -> 128 -> 40
// ---------------------------------------------------------------------------

#define NFEAT 512
#define NHID  128
#define NCLASS 40

// Scratch (allocation-free rule: __device__ globals)
__device__ float g_A[50000 * 128];   // GEMM output / SpMM input
__device__ float g_B[50000 * 128];   // SpMM output / next GEMM input
__device__ float g_C[50000 * 40];    // GEMM3 output

// ---------------------------------------------------------------------------
// Tiled fp32 SGEMM: C[M,N] = A[M,K] @ B[K,N], N == 128 exactly (one tile wide)
// BM=128, BN=128, BK=16, 256 threads, each computes 8x8.
// ---------------------------------------------------------------------------
__global__ void sgemm128(const float* __restrict__ A, const float* __restrict__ B,
                         float* __restrict__ C, int M, int K) {
    __shared__ float As[16][128];
    __shared__ float Bs[16][128];

    const int t = threadIdx.x;
    const int tRow = t >> 4;        // 0..15
    const int tCol = t & 15;        // 0..15
    const int row0 = blockIdx.y * 128;

    float acc[8][8];
#pragma unroll
    for (int i = 0; i < 8; i++)
#pragma unroll
        for (int j = 0; j < 8; j++) acc[i][j] = 0.0f;

    for (int k0 = 0; k0 < K; k0 += 16) {
        // Load A tile (128 x 16) as 512 float4; 2 per thread. Transpose into As[k][m].
#pragma unroll
        for (int l = 0; l < 2; l++) {
            int q = t + l * 256;           // 0..511
            int r = q >> 2;                // 0..127
            int c4 = q & 3;                // 0..3
            int grow = row0 + r;
            float4 v = make_float4(0.f, 0.f, 0.f, 0.f);
            if (grow < M)
                v = *reinterpret_cast<const float4*>(A + (size_t)grow * K + k0 + c4 * 4);
            As[c4 * 4 + 0][r] = v.x;
            As[c4 * 4 + 1][r] = v.y;
            As[c4 * 4 + 2][r] = v.z;
            As[c4 * 4 + 3][r] = v.w;
        }
        // Load B tile (16 x 128) as 512 float4; 2 per thread.
#pragma unroll
        for (int l = 0; l < 2; l++) {
            int q = t + l * 256;
            int r = q >> 5;                // 0..15
            int c4 = q & 31;               // 0..31
            float4 v = *reinterpret_cast<const float4*>(B + (size_t)(k0 + r) * 128 + c4 * 4);
            *reinterpret_cast<float4*>(&Bs[r][c4 * 4]) = v;
        }
        __syncthreads();

#pragma unroll
        for (int kk = 0; kk < 16; kk++) {
            float a[8], b[8];
            *reinterpret_cast<float4*>(&a[0]) = *reinterpret_cast<float4*>(&As[kk][tRow * 8]);
            *reinterpret_cast<float4*>(&a[4]) = *reinterpret_cast<float4*>(&As[kk][tRow * 8 + 4]);
            *reinterpret_cast<float4*>(&b[0]) = *reinterpret_cast<float4*>(&Bs[kk][tCol * 8]);
            *reinterpret_cast<float4*>(&b[4]) = *reinterpret_cast<float4*>(&Bs[kk][tCol * 8 + 4]);
#pragma unroll
            for (int i = 0; i < 8; i++)
#pragma unroll
                for (int j = 0; j < 8; j++)
                    acc[i][j] = fmaf(a[i], b[j], acc[i][j]);
        }
        __syncthreads();
    }

#pragma unroll
    for (int i = 0; i < 8; i++) {
        int grow = row0 + tRow * 8 + i;
        if (grow < M) {
            *reinterpret_cast<float4*>(C + (size_t)grow * 128 + tCol * 8) =
                *reinterpret_cast<float4*>(&acc[i][0]);
            *reinterpret_cast<float4*>(C + (size_t)grow * 128 + tCol * 8 + 4) =
                *reinterpret_cast<float4*>(&acc[i][4]);
        }
    }
}

// ---------------------------------------------------------------------------
// GEMM3: C[M,40] = H[M,128] @ W2[128,40]. 32 rows/block, 256 threads.
// ---------------------------------------------------------------------------
__global__ void sgemm40(const float* __restrict__ H, const float* __restrict__ W,
                        float* __restrict__ C, int M) {
    __shared__ float Ht[32][128];
    __shared__ float Ws[128][40];

    const int t = threadIdx.x;
    const int row0 = blockIdx.x * 32;

    // Load H tile (32 x 128) = 1024 float4, 4 per thread.
#pragma unroll
    for (int l = 0; l < 4; l++) {
        int q = t + l * 256;
        int r = q >> 5;
        int c4 = q & 31;
        float4 v = make_float4(0.f, 0.f, 0.f, 0.f);
        if (row0 + r < M)
            v = *reinterpret_cast<const float4*>(H + (size_t)(row0 + r) * 128 + c4 * 4);
        *reinterpret_cast<float4*>(&Ht[r][c4 * 4]) = v;
    }
    // Load W (128 x 40) = 5120 floats, 20 per thread.
#pragma unroll
    for (int l = 0; l < 20; l++) {
        int q = t + l * 256;
        Ws[q / 40][q % 40] = W[q];
    }
    __syncthreads();

    const int r = t >> 3;            // 0..31
    const int cg = t & 7;            // 0..7 -> cols cg*5 .. cg*5+4
    float acc[5] = {0.f, 0.f, 0.f, 0.f, 0.f};
#pragma unroll 8
    for (int k = 0; k < 128; k++) {
        float h = Ht[r][k];
#pragma unroll
        for (int j = 0; j < 5; j++)
            acc[j] = fmaf(h, Ws[k][cg * 5 + j], acc[j]);
    }
    int grow = row0 + r;
    if (grow < M) {
#pragma unroll
        for (int j = 0; j < 5; j++)
            C[(size_t)grow * 40 + cg * 5 + j] = acc[j];
    }
}

// ---------------------------------------------------------------------------
// SpMM (feat=128): out[dst] += w * H[src], one warp per edge, float4 per lane.
// ---------------------------------------------------------------------------
__global__ void spmm128(const float* __restrict__ H, const int* __restrict__ src,
                        const int* __restrict__ dst, const float* __restrict__ w,
                        float* __restrict__ out, int nE) {
    unsigned tid = blockIdx.x * blockDim.x + threadIdx.x;
    int e = tid >> 5;
    int q = tid & 31;
    if (e >= nE) return;
    int s = __ldg(src + e);
    int d = __ldg(dst + e);
    float ww = __ldg(w + e);
    float4 h4 = *reinterpret_cast<const float4*>(H + (size_t)s * 128 + q * 4);
    float* o = out + (size_t)d * 128 + q * 4;
    atomicAdd(o + 0, ww * h4.x);
    atomicAdd(o + 1, ww * h4.y);
    atomicAdd(o + 2, ww * h4.z);
    atomicAdd(o + 3, ww * h4.w);
}

// SpMM (feat=40): one block (64 threads) per edge, lanes 0..39 active.
__global__ void spmm40(const float* __restrict__ C, const int* __restrict__ src,
                       const int* __restrict__ dst, const float* __restrict__ w,
                       float* __restrict__ out) {
    int e = blockIdx.x;
    int f = threadIdx.x;
    if (f >= 40) return;
    int s = __ldg(src + e);
    int d = __ldg(dst + e);
    float ww = __ldg(w + e);
    atomicAdd(out + (size_t)d * 40 + f, ww * __ldg(C + (size_t)s * 40 + f));
}

// ---------------------------------------------------------------------------
// Elementwise helpers
// ---------------------------------------------------------------------------
__global__ void zero_f4(float* p, int n4) {
    int i = blockIdx.x * blockDim.x + threadIdx.x;
    if (i < n4) reinterpret_cast<float4*>(p)[i] = make_float4(0.f, 0.f, 0.f, 0.f);
}

__global__ void bias_relu128(float* __restrict__ p, const float* __restrict__ b, int n) {
    int i = blockIdx.x * blockDim.x + threadIdx.x;
    if (i < n) {
        float v = p[i] + __ldg(b + (i & 127));
        p[i] = v > 0.f ? v : 0.f;
    }
}

// log_softmax over 40 cols, in place on out (which holds Z3), adding b2.
__global__ void logsoftmax40(float* __restrict__ out, const float* __restrict__ b, int M) {
    int row = blockIdx.x * 8 + (threadIdx.x >> 5);
    int lane = threadIdx.x & 31;
    if (row >= M) return;
    float v0 = out[(size_t)row * 40 + lane] + __ldg(b + lane);
    float v1 = -INFINITY;
    if (lane < 8) v1 = out[(size_t)row * 40 + 32 + lane] + __ldg(b + 32 + lane);
    float m = fmaxf(v0, v1);
#pragma unroll
    for (int o = 16; o > 0; o >>= 1) m = fmaxf(m, __shfl_xor_sync(0xffffffffu, m, o));
    float s = __expf(v0 - m) + (lane < 8 ? __expf(v1 - m) : 0.f);
#pragma unroll
    for (int o = 16; o > 0; o >>= 1) s += __shfl_xor_sync(0xffffffffu, s, o);
    float ls = m + __logf(s);
    out[(size_t)row * 40 + lane] = v0 - ls;
    if (lane < 8) out[(size_t)row * 40 + 32 + lane] = v1 - ls;
}

// ---------------------------------------------------------------------------
extern "C" void kernel_launch(void* const* d_in, const int* in_sizes, int n_in,
                              void* d_out, int out_size) {
    const float* x    = (const float*)d_in[0];
    const int*   esrc = (const int*)  d_in[1];
    const int*   edst = (const int*)  d_in[2];
    const float* ew   = (const float*)d_in[3];
    const float* W1   = (const float*)d_in[4];
    const float* b1   = (const float*)d_in[5];
    const float* Wh   = (const float*)d_in[6];
    const float* bh   = (const float*)d_in[7];
    const float* W2   = (const float*)d_in[8];
    const float* b2   = (const float*)d_in[9];
    float* out = (float*)d_out;

    const int M  = in_sizes[0] / NFEAT;   // 50000
    const int nE = in_sizes[1];           // 1600000

    float *A, *B, *C;
    cudaGetSymbolAddress((void**)&A, g_A);
    cudaGetSymbolAddress((void**)&B, g_B);
    cudaGetSymbolAddress((void**)&C, g_C);

    const int gemmBlocksY = (M + 127) / 128;
    const int nH = M * NHID;

    // Layer 1: A = x @ W1 ; B = spmm(A) ; B = relu(B + b1)
    sgemm128<<<dim3(1, gemmBlocksY), 256>>>(x, W1, A, M, NFEAT);
    zero_f4<<<(nH / 4 + 255) / 256, 256>>>(B, nH / 4);
    {
        unsigned total = (unsigned)nE * 32u;
        spmm128<<<(total + 255) / 256, 256>>>(A, esrc, edst, ew, B, nE);
    }
    bias_relu128<<<(nH + 255) / 256, 256>>>(B, b1, nH);

    // Layer 2: A = B @ Wh ; B = spmm(A) ; B = relu(B + bh)
    sgemm128<<<dim3(1, gemmBlocksY), 256>>>(B, Wh, A, M, NHID);
    zero_f4<<<(nH / 4 + 255) / 256, 256>>>(B, nH / 4);
    {
        unsigned total = (unsigned)nE * 32u;
        spmm128<<<(total + 255) / 256, 256>>>(A, esrc, edst, ew, B, nE);
    }
    bias_relu128<<<(nH + 255) / 256, 256>>>(B, bh, nH);

    // Layer 3: C = B @ W2 ; out = spmm(C) ; out = log_softmax(out + b2)
    sgemm40<<<(M + 31) / 32, 256>>>(B, W2, C, M);
    {
        int n4 = M * NCLASS / 4;
        zero_f4<<<(n4 + 255) / 256, 256>>>(out, n4);
    }
    spmm40<<<nE, 64>>>(C, esrc, edst, ew, out);
    logsoftmax40<<<(M + 7) / 8, 256>>>(out, b2, M);
}

// round 2
// speedup vs baseline: 4.0563x; 4.0563x over previous
#include <cuda_runtime.h>
#include <cuda_bf16.h>
#include <math.h>

// ---------------------------------------------------------------------------
// GCN: 3x { H = A_sparse @ (H @ W) + b (,ReLU) } -> log_softmax
// N=50000 nodes, E=1.6M edges, 512 -> 128 -> 128 -> 40
// Strategy: dense tiled SGEMM + on-device CSR build (counting sort by dst)
//           + atomic-free gather SpMM with fused bias/ReLU/log_softmax.
// ---------------------------------------------------------------------------

#define NNODES 50000
#define NEDGES 1600000
#define NFEAT 512
#define NHID  128
#define NCLASS 40

// Scratch (allocation-free rule: __device__ globals)
__device__ float g_A[NNODES * NHID];     // GEMM output / SpMM input
__device__ float g_B[NNODES * NHID];     // SpMM output / next GEMM input
__device__ float g_C[NNODES * NCLASS];   // GEMM3 output
__device__ int   g_cnt[NNODES];          // histogram
__device__ int   g_cursor[NNODES];       // scatter cursors
__device__ int   g_rp[NNODES + 1];       // CSR row pointers (by dst)
__device__ int   g_psrc[NEDGES];         // permuted src
__device__ float g_pw[NEDGES];           // permuted weight

// ---------------------------------------------------------------------------
// CSR build: zero -> histogram(dst) -> scan -> scatter
// ---------------------------------------------------------------------------
__global__ void zero_int(int* p, int n) {
    int i = blockIdx.x * blockDim.x + threadIdx.x;
    if (i < n) p[i] = 0;
}

__global__ void hist_dst(const int* __restrict__ dst, int* __restrict__ cnt, int nE) {
    int e = blockIdx.x * blockDim.x + threadIdx.x;
    if (e < nE) atomicAdd(&cnt[dst[e]], 1);
}

// Single-block exclusive scan over n counters; writes rp[0..n] and cursor[0..n).
__global__ void scan_rows(const int* __restrict__ cnt, int* __restrict__ rp,
                          int* __restrict__ cursor, int n) {
    __shared__ int wsum[32];
    __shared__ int carry_s;
    const int lane = threadIdx.x & 31;
    const int wid  = threadIdx.x >> 5;
    const int nw   = blockDim.x >> 5;
    if (threadIdx.x == 0) carry_s = 0;
    __syncthreads();
    for (int base = 0; base < n; base += blockDim.x) {
        int i = base + threadIdx.x;
        int v = (i < n) ? cnt[i] : 0;
        int incl = v;
#pragma unroll
        for (int o = 1; o < 32; o <<= 1) {
            int t = __shfl_up_sync(0xffffffffu, incl, o);
            if (lane >= o) incl += t;
        }
        if (lane == 31) wsum[wid] = incl;
        __syncthreads();
        if (wid == 0) {
            int s = (lane < nw) ? wsum[lane] : 0;
#pragma unroll
            for (int o = 1; o < 32; o <<= 1) {
                int t = __shfl_up_sync(0xffffffffu, s, o);
                if (lane >= o) s += t;
            }
            wsum[lane] = s;
        }
        __syncthreads();
        int carry = carry_s;
        int excl = carry + (wid ? wsum[wid - 1] : 0) + incl - v;
        if (i < n) { rp[i] = excl; cursor[i] = excl; }
        __syncthreads();
        if (threadIdx.x == 0) carry_s = carry + wsum[nw - 1];
        __syncthreads();
    }
    if (threadIdx.x == 0) rp[n] = carry_s;
}

__global__ void scatter_edges(const int* __restrict__ src, const int* __restrict__ dst,
                              const float* __restrict__ w, int* __restrict__ cursor,
                              int* __restrict__ psrc, float* __restrict__ pw, int nE) {
    int e = blockIdx.x * blockDim.x + threadIdx.x;
    if (e >= nE) return;
    int d = dst[e];
    int pos = atomicAdd(&cursor[d], 1);
    psrc[pos] = src[e];
    pw[pos]   = w[e];
}

// ---------------------------------------------------------------------------
// Tiled fp32 SGEMM: C[M,128] = A[M,K] @ B[K,128]
// ---------------------------------------------------------------------------
__global__ void sgemm128(const float* __restrict__ A, const float* __restrict__ B,
                         float* __restrict__ C, int M, int K) {
    __shared__ float As[16][128];
    __shared__ float Bs[16][128];

    const int t = threadIdx.x;
    const int tRow = t >> 4;
    const int tCol = t & 15;
    const int row0 = blockIdx.y * 128;

    float acc[8][8];
#pragma unroll
    for (int i = 0; i < 8; i++)
#pragma unroll
        for (int j = 0; j < 8; j++) acc[i][j] = 0.0f;

    for (int k0 = 0; k0 < K; k0 += 16) {
#pragma unroll
        for (int l = 0; l < 2; l++) {
            int q = t + l * 256;
            int r = q >> 2;
            int c4 = q & 3;
            int grow = row0 + r;
            float4 v = make_float4(0.f, 0.f, 0.f, 0.f);
            if (grow < M)
                v = *reinterpret_cast<const float4*>(A + (size_t)grow * K + k0 + c4 * 4);
            As[c4 * 4 + 0][r] = v.x;
            As[c4 * 4 + 1][r] = v.y;
            As[c4 * 4 + 2][r] = v.z;
            As[c4 * 4 + 3][r] = v.w;
        }
#pragma unroll
        for (int l = 0; l < 2; l++) {
            int q = t + l * 256;
            int r = q >> 5;
            int c4 = q & 31;
            float4 v = *reinterpret_cast<const float4*>(B + (size_t)(k0 + r) * 128 + c4 * 4);
            *reinterpret_cast<float4*>(&Bs[r][c4 * 4]) = v;
        }
        __syncthreads();

#pragma unroll
        for (int kk = 0; kk < 16; kk++) {
            float a[8], b[8];
            *reinterpret_cast<float4*>(&a[0]) = *reinterpret_cast<float4*>(&As[kk][tRow * 8]);
            *reinterpret_cast<float4*>(&a[4]) = *reinterpret_cast<float4*>(&As[kk][tRow * 8 + 4]);
            *reinterpret_cast<float4*>(&b[0]) = *reinterpret_cast<float4*>(&Bs[kk][tCol * 8]);
            *reinterpret_cast<float4*>(&b[4]) = *reinterpret_cast<float4*>(&Bs[kk][tCol * 8 + 4]);
#pragma unroll
            for (int i = 0; i < 8; i++)
#pragma unroll
                for (int j = 0; j < 8; j++)
                    acc[i][j] = fmaf(a[i], b[j], acc[i][j]);
        }
        __syncthreads();
    }

#pragma unroll
    for (int i = 0; i < 8; i++) {
        int grow = row0 + tRow * 8 + i;
        if (grow < M) {
            *reinterpret_cast<float4*>(C + (size_t)grow * 128 + tCol * 8) =
                *reinterpret_cast<float4*>(&acc[i][0]);
            *reinterpret_cast<float4*>(C + (size_t)grow * 128 + tCol * 8 + 4) =
                *reinterpret_cast<float4*>(&acc[i][4]);
        }
    }
}

// ---------------------------------------------------------------------------
// GEMM3: C[M,40] = H[M,128] @ W2[128,40]
// ---------------------------------------------------------------------------
__global__ void sgemm40(const float* __restrict__ H, const float* __restrict__ W,
                        float* __restrict__ C, int M) {
    __shared__ float Ht[32][128];
    __shared__ float Ws[128][40];

    const int t = threadIdx.x;
    const int row0 = blockIdx.x * 32;

#pragma unroll
    for (int l = 0; l < 4; l++) {
        int q = t + l * 256;
        int r = q >> 5;
        int c4 = q & 31;
        float4 v = make_float4(0.f, 0.f, 0.f, 0.f);
        if (row0 + r < M)
            v = *reinterpret_cast<const float4*>(H + (size_t)(row0 + r) * 128 + c4 * 4);
        *reinterpret_cast<float4*>(&Ht[r][c4 * 4]) = v;
    }
#pragma unroll
    for (int l = 0; l < 20; l++) {
        int q = t + l * 256;
        Ws[q / 40][q % 40] = W[q];
    }
    __syncthreads();

    const int r = t >> 3;
    const int cg = t & 7;
    float acc[5] = {0.f, 0.f, 0.f, 0.f, 0.f};
#pragma unroll 8
    for (int k = 0; k < 128; k++) {
        float h = Ht[r][k];
#pragma unroll
        for (int j = 0; j < 5; j++)
            acc[j] = fmaf(h, Ws[k][cg * 5 + j], acc[j]);
    }
    int grow = row0 + r;
    if (grow < M) {
#pragma unroll
        for (int j = 0; j < 5; j++)
            C[(size_t)grow * 40 + cg * 5 + j] = acc[j];
    }
}

// ---------------------------------------------------------------------------
// Gather SpMM (feat=128): one warp per dst row, float4 per lane, unroll 4.
// Epilogue: out = relu(acc + bias)
// ---------------------------------------------------------------------------
__global__ void __launch_bounds__(256) spmm_csr128(
    const float* __restrict__ H, const int* __restrict__ rp,
    const int* __restrict__ psrc, const float* __restrict__ pw,
    const float* __restrict__ bias, float* __restrict__ out, int M) {
    int row = blockIdx.x * 8 + (threadIdx.x >> 5);
    int lane = threadIdx.x & 31;
    if (row >= M) return;
    int p  = __ldg(rp + row);
    int pe = __ldg(rp + row + 1);

    const float* Hb = H + lane * 4;
    float ax = 0.f, ay = 0.f, az = 0.f, aw = 0.f;

    for (; p + 4 <= pe; p += 4) {
        int s0 = __ldg(psrc + p + 0), s1 = __ldg(psrc + p + 1);
        int s2 = __ldg(psrc + p + 2), s3 = __ldg(psrc + p + 3);
        float w0 = __ldg(pw + p + 0), w1 = __ldg(pw + p + 1);
        float w2 = __ldg(pw + p + 2), w3 = __ldg(pw + p + 3);
        float4 h0 = *reinterpret_cast<const float4*>(Hb + (size_t)s0 * 128);
        float4 h1 = *reinterpret_cast<const float4*>(Hb + (size_t)s1 * 128);
        float4 h2 = *reinterpret_cast<const float4*>(Hb + (size_t)s2 * 128);
        float4 h3 = *reinterpret_cast<const float4*>(Hb + (size_t)s3 * 128);
        ax = fmaf(w0, h0.x, ax); ay = fmaf(w0, h0.y, ay); az = fmaf(w0, h0.z, az); aw = fmaf(w0, h0.w, aw);
        ax = fmaf(w1, h1.x, ax); ay = fmaf(w1, h1.y, ay); az = fmaf(w1, h1.z, az); aw = fmaf(w1, h1.w, aw);
        ax = fmaf(w2, h2.x, ax); ay = fmaf(w2, h2.y, ay); az = fmaf(w2, h2.z, az); aw = fmaf(w2, h2.w, aw);
        ax = fmaf(w3, h3.x, ax); ay = fmaf(w3, h3.y, ay); az = fmaf(w3, h3.z, az); aw = fmaf(w3, h3.w, aw);
    }
    for (; p < pe; p++) {
        int s = __ldg(psrc + p);
        float w = __ldg(pw + p);
        float4 h = *reinterpret_cast<const float4*>(Hb + (size_t)s * 128);
        ax = fmaf(w, h.x, ax); ay = fmaf(w, h.y, ay); az = fmaf(w, h.z, az); aw = fmaf(w, h.w, aw);
    }

    float4 b4 = *reinterpret_cast<const float4*>(bias + lane * 4);
    float4 r4;
    r4.x = fmaxf(ax + b4.x, 0.f);
    r4.y = fmaxf(ay + b4.y, 0.f);
    r4.z = fmaxf(az + b4.z, 0.f);
    r4.w = fmaxf(aw + b4.w, 0.f);
    *reinterpret_cast<float4*>(out + (size_t)row * 128 + lane * 4) = r4;
}

// ---------------------------------------------------------------------------
// Gather SpMM (feat=40) + bias + log_softmax, one warp per dst row.
// Lane l owns col l; lanes 0..7 also own col 32+l.
// ---------------------------------------------------------------------------
__global__ void __launch_bounds__(256) spmm_csr40_lsm(
    const float* __restrict__ C, const int* __restrict__ rp,
    const int* __restrict__ psrc, const float* __restrict__ pw,
    const float* __restrict__ b, float* __restrict__ out, int M) {
    int row = blockIdx.x * 8 + (threadIdx.x >> 5);
    int lane = threadIdx.x & 31;
    if (row >= M) return;
    int p  = __ldg(rp + row);
    int pe = __ldg(rp + row + 1);

    float a0 = 0.f, a1 = 0.f;
    for (; p + 2 <= pe; p += 2) {
        int s0 = __ldg(psrc + p), s1 = __ldg(psrc + p + 1);
        float w0 = __ldg(pw + p), w1 = __ldg(pw + p + 1);
        const float* c0 = C + (size_t)s0 * 40;
        const float* c1 = C + (size_t)s1 * 40;
        float x0 = __ldg(c0 + lane);
        float x1 = __ldg(c1 + lane);
        float y0 = (lane < 8) ? __ldg(c0 + 32 + lane) : 0.f;
        float y1 = (lane < 8) ? __ldg(c1 + 32 + lane) : 0.f;
        a0 = fmaf(w0, x0, a0); a0 = fmaf(w1, x1, a0);
        a1 = fmaf(w0, y0, a1); a1 = fmaf(w1, y1, a1);
    }
    if (p < pe) {
        int s = __ldg(psrc + p);
        float w = __ldg(pw + p);
        const float* c0 = C + (size_t)s * 40;
        a0 = fmaf(w, __ldg(c0 + lane), a0);
        if (lane < 8) a1 = fmaf(w, __ldg(c0 + 32 + lane), a1);
    }

    float v0 = a0 + __ldg(b + lane);
    float v1 = (lane < 8) ? (a1 + __ldg(b + 32 + lane)) : -INFINITY;

    float m = fmaxf(v0, v1);
#pragma unroll
    for (int o = 16; o > 0; o >>= 1) m = fmaxf(m, __shfl_xor_sync(0xffffffffu, m, o));
    float s = __expf(v0 - m) + ((lane < 8) ? __expf(v1 - m) : 0.f);
#pragma unroll
    for (int o = 16; o > 0; o >>= 1) s += __shfl_xor_sync(0xffffffffu, s, o);
    float ls = m + __logf(s);

    out[(size_t)row * 40 + lane] = v0 - ls;
    if (lane < 8) out[(size_t)row * 40 + 32 + lane] = v1 - ls;
}

// ---------------------------------------------------------------------------
extern "C" void kernel_launch(void* const* d_in, const int* in_sizes, int n_in,
                              void* d_out, int out_size) {
    const float* x    = (const float*)d_in[0];
    const int*   esrc = (const int*)  d_in[1];
    const int*   edst = (const int*)  d_in[2];
    const float* ew   = (const float*)d_in[3];
    const float* W1   = (const float*)d_in[4];
    const float* b1   = (const float*)d_in[5];
    const float* Wh   = (const float*)d_in[6];
    const float* bh   = (const float*)d_in[7];
    const float* W2   = (const float*)d_in[8];
    const float* b2   = (const float*)d_in[9];
    float* out = (float*)d_out;

    const int M  = in_sizes[0] / NFEAT;   // 50000
    const int nE = in_sizes[1];           // 1600000

    float *A, *B, *C, *pw;
    int *cnt, *cursor, *rp, *psrc;
    cudaGetSymbolAddress((void**)&A, g_A);
    cudaGetSymbolAddress((void**)&B, g_B);
    cudaGetSymbolAddress((void**)&C, g_C);
    cudaGetSymbolAddress((void**)&cnt, g_cnt);
    cudaGetSymbolAddress((void**)&cursor, g_cursor);
    cudaGetSymbolAddress((void**)&rp, g_rp);
    cudaGetSymbolAddress((void**)&psrc, g_psrc);
    cudaGetSymbolAddress((void**)&pw, g_pw);

    // ---- CSR build (counting sort by dst), reused by all 3 SpMMs ----
    zero_int<<<(M + 255) / 256, 256>>>(cnt, M);
    hist_dst<<<(nE + 255) / 256, 256>>>(edst, cnt, nE);
    scan_rows<<<1, 1024>>>(cnt, rp, cursor, M);
    scatter_edges<<<(nE + 255) / 256, 256>>>(esrc, edst, ew, cursor, psrc, pw, nE);

    const int gemmBlocksY = (M + 127) / 128;
    const int spmmBlocks  = (M + 7) / 8;

    // Layer 1
    sgemm128<<<dim3(1, gemmBlocksY), 256>>>(x, W1, A, M, NFEAT);
    spmm_csr128<<<spmmBlocks, 256>>>(A, rp, psrc, pw, b1, B, M);

    // Layer 2
    sgemm128<<<dim3(1, gemmBlocksY), 256>>>(B, Wh, A, M, NHID);
    spmm_csr128<<<spmmBlocks, 256>>>(A, rp, psrc, pw, bh, B, M);

    // Layer 3 + log_softmax
    sgemm40<<<(M + 31) / 32, 256>>>(B, W2, C, M);
    spmm_csr40_lsm<<<spmmBlocks, 256>>>(C, rp, psrc, pw, b2, out, M);
}

// round 4
// speedup vs baseline: 5.0742x; 1.2510x over previous
#include <cuda_runtime.h>
#include <cuda_bf16.h>
#include <math.h>
#include <cstdint>

// ---------------------------------------------------------------------------
// GCN: 3x { H = A_sparse @ (H @ W) + b (,ReLU) } -> log_softmax
// N=50000, E=1.6M, 512 -> 128 -> 128 -> 40
// Round 4: mma.sync (HMMA) bf16 hi/lo split GEMM (arch-portable PTX; tcgen05
//          is unavailable because harness PTX targets compute_103, not 103a),
//          CSR gather SpMM (atomic-free), packed int2 edge records.
// ---------------------------------------------------------------------------

#define NNODES 50000
#define NEDGES 1600000
#define NFEAT 512
#define NHID  128
#define NCLASS 40

// Scratch (__device__ globals; no allocations allowed)
__device__ float g_A[NNODES * NHID];
__device__ float g_B[NNODES * NHID];
__device__ float g_C[NNODES * NCLASS];
__device__ int   g_cnt[NNODES];
__device__ int   g_cursor[NNODES];
__device__ int   g_rp[NNODES + 1];
__device__ int2  g_pe[NEDGES];          // packed (src, weight-bits)

// ===========================================================================
// bf16 hi/lo helpers
// ===========================================================================
__device__ __forceinline__ void cvt_hilo(float x, float y, uint32_t& hi, uint32_t& lo) {
    __nv_bfloat16 hx = __float2bfloat16(x);
    __nv_bfloat16 hy = __float2bfloat16(y);
    float rx = x - __bfloat162float(hx);
    float ry = y - __bfloat162float(hy);
    __nv_bfloat162 H; H.x = hx; H.y = hy;
    __nv_bfloat162 L; L.x = __float2bfloat16(rx); L.y = __float2bfloat16(ry);
    hi = *reinterpret_cast<uint32_t*>(&H);
    lo = *reinterpret_cast<uint32_t*>(&L);
}

__device__ __forceinline__ void mma16816(float* d, const uint32_t* a, uint32_t b0, uint32_t b1) {
    asm volatile(
        "mma.sync.aligned.m16n8k16.row.col.f32.bf16.bf16.f32 "
        "{%0,%1,%2,%3}, {%4,%5,%6,%7}, {%8,%9}, {%0,%1,%2,%3};"
        : "+f"(d[0]), "+f"(d[1]), "+f"(d[2]), "+f"(d[3])
        : "r"(a[0]), "r"(a[1]), "r"(a[2]), "r"(a[3]), "r"(b0), "r"(b1));
}

// SMEM layout (u32 units). A tiles: [m=128][k2=32 + pad4] (pairs of k).
// B tiles: [k2=32][n=128 + pad8]. Bank-conflict-free for both frag patterns.
#define AH_OFF 0
#define AL_OFF 4608
#define BH_OFF 9216
#define BL_OFF 13568
#define SM_U32 17920   // 71680 bytes

// ===========================================================================
// mma.sync GEMM: C[M,128] = A[M,K] @ W[K,128], fp32 in/out, hi/lo bf16 split.
// CTA: 128 rows x 128 cols, 8 warps in 4x2, warp tile 32x64. K chunks of 64.
// ===========================================================================
__global__ void __launch_bounds__(256) mma_gemm128(
    const float* __restrict__ A, const float* __restrict__ W,
    float* __restrict__ C, int M, int K) {
    extern __shared__ uint32_t sm[];
    uint32_t* AH = sm + AH_OFF;
    uint32_t* AL = sm + AL_OFF;
    uint32_t* BH = sm + BH_OFF;
    uint32_t* BL = sm + BL_OFF;

    const int t = threadIdx.x;
    const int lane = t & 31;
    const int wid = t >> 5;
    const int warpM = wid >> 1;           // 0..3
    const int warpN = wid & 1;            // 0..1
    const int row0 = blockIdx.x * 128;

    float acc[2][8][4];
#pragma unroll
    for (int mt = 0; mt < 2; mt++)
#pragma unroll
        for (int nt = 0; nt < 8; nt++)
#pragma unroll
            for (int e = 0; e < 4; e++) acc[mt][nt][e] = 0.f;

    const int r4 = lane >> 2;             // 0..7
    const int q4 = lane & 3;              // 0..3

    const int nChunks = K >> 6;
    for (int c = 0; c < nChunks; c++) {
        const int k0 = c << 6;
        __syncthreads();   // protect SMEM reuse across chunks

        // ---- stage A chunk: 128 rows x 64 k, fp32 -> hi/lo bf16x2 pairs ----
#pragma unroll
        for (int l = 0; l < 8; l++) {
            int q = t + l * 256;          // 0..2047 float4 slots
            int m = q >> 4;               // 0..127
            int c4 = q & 15;              // 0..15 (float4 within 64 k)
            float4 v = make_float4(0.f, 0.f, 0.f, 0.f);
            if (row0 + m < M)
                v = *reinterpret_cast<const float4*>(A + (size_t)(row0 + m) * K + k0 + c4 * 4);
            uint32_t h0, l0, h1, l1;
            cvt_hilo(v.x, v.y, h0, l0);
            cvt_hilo(v.z, v.w, h1, l1);
            int base = m * 36 + c4 * 2;
            AH[base] = h0; AH[base + 1] = h1;
            AL[base] = l0; AL[base + 1] = l1;
        }
        // ---- stage B chunk: W[k0..k0+63][0..127] -> k-pair packed ----
#pragma unroll
        for (int l = 0; l < 16; l++) {
            int p = t + l * 256;          // 0..4095 pairs
            int k2 = p >> 7;              // 0..31
            int n = p & 127;              // 0..127
            float v0 = __ldg(W + (size_t)(k0 + 2 * k2) * 128 + n);
            float v1 = __ldg(W + (size_t)(k0 + 2 * k2 + 1) * 128 + n);
            uint32_t h, lo;
            cvt_hilo(v0, v1, h, lo);
            BH[k2 * 136 + n] = h;
            BL[k2 * 136 + n] = lo;
        }
        __syncthreads();

        // ---- 4 k16 steps per chunk ----
#pragma unroll
        for (int k8 = 0; k8 < 4; k8++) {
            int klo = k8 * 8 + q4;
            uint32_t ah[2][4], al[2][4];
#pragma unroll
            for (int mt = 0; mt < 2; mt++) {
                int base = (warpM * 32 + mt * 16 + r4) * 36;
                ah[mt][0] = AH[base + klo];
                ah[mt][1] = AH[base + 8 * 36 + klo];
                ah[mt][2] = AH[base + klo + 4];
                ah[mt][3] = AH[base + 8 * 36 + klo + 4];
                al[mt][0] = AL[base + klo];
                al[mt][1] = AL[base + 8 * 36 + klo];
                al[mt][2] = AL[base + klo + 4];
                al[mt][3] = AL[base + 8 * 36 + klo + 4];
            }
#pragma unroll
            for (int nt = 0; nt < 8; nt++) {
                int nB = warpN * 64 + nt * 8 + r4;
                uint32_t bh0 = BH[klo * 136 + nB];
                uint32_t bh1 = BH[(klo + 4) * 136 + nB];
                uint32_t bl0 = BL[klo * 136 + nB];
                uint32_t bl1 = BL[(klo + 4) * 136 + nB];
#pragma unroll
                for (int mt = 0; mt < 2; mt++) {
                    mma16816(acc[mt][nt], ah[mt], bh0, bh1);
                    mma16816(acc[mt][nt], ah[mt], bl0, bl1);
                    mma16816(acc[mt][nt], al[mt], bh0, bh1);
                }
            }
        }
    }

    // ---- epilogue: write fp32 ----
#pragma unroll
    for (int mt = 0; mt < 2; mt++) {
        int rowA = row0 + warpM * 32 + mt * 16 + r4;
        int rowB = rowA + 8;
#pragma unroll
        for (int nt = 0; nt < 8; nt++) {
            int col = warpN * 64 + nt * 8 + q4 * 2;
            if (rowA < M)
                *reinterpret_cast<float2*>(C + (size_t)rowA * 128 + col) =
                    make_float2(acc[mt][nt][0], acc[mt][nt][1]);
            if (rowB < M)
                *reinterpret_cast<float2*>(C + (size_t)rowB * 128 + col) =
                    make_float2(acc[mt][nt][2], acc[mt][nt][3]);
        }
    }
}

// ===========================================================================
// CSR build
// ===========================================================================
__global__ void zero_int(int* p, int n) {
    int i = blockIdx.x * blockDim.x + threadIdx.x;
    if (i < n) p[i] = 0;
}

__global__ void hist_dst(const int* __restrict__ dst, int* __restrict__ cnt, int nE) {
    int e = blockIdx.x * blockDim.x + threadIdx.x;
    if (e < nE) atomicAdd(&cnt[dst[e]], 1);
}

__global__ void scan_rows(const int* __restrict__ cnt, int* __restrict__ rp,
                          int* __restrict__ cursor, int n) {
    __shared__ int wsum[32];
    __shared__ int carry_s;
    const int lane = threadIdx.x & 31;
    const int wid  = threadIdx.x >> 5;
    const int nw   = blockDim.x >> 5;
    if (threadIdx.x == 0) carry_s = 0;
    __syncthreads();
    for (int base = 0; base < n; base += blockDim.x) {
        int i = base + threadIdx.x;
        int v = (i < n) ? cnt[i] : 0;
        int incl = v;
#pragma unroll
        for (int o = 1; o < 32; o <<= 1) {
            int t = __shfl_up_sync(0xffffffffu, incl, o);
            if (lane >= o) incl += t;
        }
        if (lane == 31) wsum[wid] = incl;
        __syncthreads();
        if (wid == 0) {
            int s = (lane < nw) ? wsum[lane] : 0;
#pragma unroll
            for (int o = 1; o < 32; o <<= 1) {
                int t = __shfl_up_sync(0xffffffffu, s, o);
                if (lane >= o) s += t;
            }
            wsum[lane] = s;
        }
        __syncthreads();
        int carry = carry_s;
        int excl = carry + (wid ? wsum[wid - 1] : 0) + incl - v;
        if (i < n) { rp[i] = excl; cursor[i] = excl; }
        __syncthreads();
        if (threadIdx.x == 0) carry_s = carry + wsum[nw - 1];
        __syncthreads();
    }
    if (threadIdx.x == 0) rp[n] = carry_s;
}

__global__ void scatter_edges(const int* __restrict__ src, const int* __restrict__ dst,
                              const float* __restrict__ w, int* __restrict__ cursor,
                              int2* __restrict__ pe, int nE) {
    int e = blockIdx.x * blockDim.x + threadIdx.x;
    if (e >= nE) return;
    int d = dst[e];
    int pos = atomicAdd(&cursor[d], 1);
    pe[pos] = make_int2(src[e], __float_as_int(w[e]));
}

// ===========================================================================
// GEMM3: C[M,40] = H[M,128] @ W2[128,40]
// ===========================================================================
__global__ void sgemm40(const float* __restrict__ H, const float* __restrict__ W,
                        float* __restrict__ C, int M) {
    __shared__ float Ht[32][128];
    __shared__ float Ws[128][40];

    const int t = threadIdx.x;
    const int row0 = blockIdx.x * 32;

#pragma unroll
    for (int l = 0; l < 4; l++) {
        int q = t + l * 256;
        int r = q >> 5;
        int c4 = q & 31;
        float4 v = make_float4(0.f, 0.f, 0.f, 0.f);
        if (row0 + r < M)
            v = *reinterpret_cast<const float4*>(H + (size_t)(row0 + r) * 128 + c4 * 4);
        *reinterpret_cast<float4*>(&Ht[r][c4 * 4]) = v;
    }
#pragma unroll
    for (int l = 0; l < 20; l++) {
        int q = t + l * 256;
        Ws[q / 40][q % 40] = W[q];
    }
    __syncthreads();

    const int r = t >> 3;
    const int cg = t & 7;
    float acc[5] = {0.f, 0.f, 0.f, 0.f, 0.f};
#pragma unroll 8
    for (int k = 0; k < 128; k++) {
        float h = Ht[r][k];
#pragma unroll
        for (int j = 0; j < 5; j++)
            acc[j] = fmaf(h, Ws[k][cg * 5 + j], acc[j]);
    }
    int grow = row0 + r;
    if (grow < M) {
#pragma unroll
        for (int j = 0; j < 5; j++)
            C[(size_t)grow * 40 + cg * 5 + j] = acc[j];
    }
}

// ===========================================================================
// Gather SpMM (feat=128) + bias + ReLU
// ===========================================================================
__global__ void __launch_bounds__(256) spmm_csr128(
    const float* __restrict__ H, const int* __restrict__ rp,
    const int2* __restrict__ pe, const float* __restrict__ bias,
    float* __restrict__ out, int M) {
    int row = blockIdx.x * 8 + (threadIdx.x >> 5);
    int lane = threadIdx.x & 31;
    if (row >= M) return;
    int p  = __ldg(rp + row);
    int pend = __ldg(rp + row + 1);

    const float* Hb = H + lane * 4;
    float ax = 0.f, ay = 0.f, az = 0.f, aw = 0.f;

    for (; p + 4 <= pend; p += 4) {
        int2 e0 = __ldg(pe + p + 0), e1 = __ldg(pe + p + 1);
        int2 e2 = __ldg(pe + p + 2), e3 = __ldg(pe + p + 3);
        float w0 = __int_as_float(e0.y), w1 = __int_as_float(e1.y);
        float w2 = __int_as_float(e2.y), w3 = __int_as_float(e3.y);
        float4 h0 = *reinterpret_cast<const float4*>(Hb + (size_t)e0.x * 128);
        float4 h1 = *reinterpret_cast<const float4*>(Hb + (size_t)e1.x * 128);
        float4 h2 = *reinterpret_cast<const float4*>(Hb + (size_t)e2.x * 128);
        float4 h3 = *reinterpret_cast<const float4*>(Hb + (size_t)e3.x * 128);
        ax = fmaf(w0, h0.x, ax); ay = fmaf(w0, h0.y, ay); az = fmaf(w0, h0.z, az); aw = fmaf(w0, h0.w, aw);
        ax = fmaf(w1, h1.x, ax); ay = fmaf(w1, h1.y, ay); az = fmaf(w1, h1.z, az); aw = fmaf(w1, h1.w, aw);
        ax = fmaf(w2, h2.x, ax); ay = fmaf(w2, h2.y, ay); az = fmaf(w2, h2.z, az); aw = fmaf(w2, h2.w, aw);
        ax = fmaf(w3, h3.x, ax); ay = fmaf(w3, h3.y, ay); az = fmaf(w3, h3.z, az); aw = fmaf(w3, h3.w, aw);
    }
    for (; p < pend; p++) {
        int2 e = __ldg(pe + p);
        float w = __int_as_float(e.y);
        float4 h = *reinterpret_cast<const float4*>(Hb + (size_t)e.x * 128);
        ax = fmaf(w, h.x, ax); ay = fmaf(w, h.y, ay); az = fmaf(w, h.z, az); aw = fmaf(w, h.w, aw);
    }

    float4 b4 = *reinterpret_cast<const float4*>(bias + lane * 4);
    float4 r4;
    r4.x = fmaxf(ax + b4.x, 0.f);
    r4.y = fmaxf(ay + b4.y, 0.f);
    r4.z = fmaxf(az + b4.z, 0.f);
    r4.w = fmaxf(aw + b4.w, 0.f);
    *reinterpret_cast<float4*>(out + (size_t)row * 128 + lane * 4) = r4;
}

// ===========================================================================
// Gather SpMM (feat=40) + bias + log_softmax
// ===========================================================================
__global__ void __launch_bounds__(256) spmm_csr40_lsm(
    const float* __restrict__ C, const int* __restrict__ rp,
    const int2* __restrict__ pe, const float* __restrict__ b,
    float* __restrict__ out, int M) {
    int row = blockIdx.x * 8 + (threadIdx.x >> 5);
    int lane = threadIdx.x & 31;
    if (row >= M) return;
    int p  = __ldg(rp + row);
    int pend = __ldg(rp + row + 1);

    float a0 = 0.f, a1 = 0.f;
    for (; p + 2 <= pend; p += 2) {
        int2 e0 = __ldg(pe + p), e1 = __ldg(pe + p + 1);
        float w0 = __int_as_float(e0.y), w1 = __int_as_float(e1.y);
        const float* c0 = C + (size_t)e0.x * 40;
        const float* c1 = C + (size_t)e1.x * 40;
        float x0 = __ldg(c0 + lane);
        float x1 = __ldg(c1 + lane);
        float y0 = (lane < 8) ? __ldg(c0 + 32 + lane) : 0.f;
        float y1 = (lane < 8) ? __ldg(c1 + 32 + lane) : 0.f;
        a0 = fmaf(w0, x0, a0); a0 = fmaf(w1, x1, a0);
        a1 = fmaf(w0, y0, a1); a1 = fmaf(w1, y1, a1);
    }
    if (p < pend) {
        int2 e = __ldg(pe + p);
        float w = __int_as_float(e.y);
        const float* c0 = C + (size_t)e.x * 40;
        a0 = fmaf(w, __ldg(c0 + lane), a0);
        if (lane < 8) a1 = fmaf(w, __ldg(c0 + 32 + lane), a1);
    }

    float v0 = a0 + __ldg(b + lane);
    float v1 = (lane < 8) ? (a1 + __ldg(b + 32 + lane)) : -INFINITY;

    float m = fmaxf(v0, v1);
#pragma unroll
    for (int o = 16; o > 0; o >>= 1) m = fmaxf(m, __shfl_xor_sync(0xffffffffu, m, o));
    float s = __expf(v0 - m) + ((lane < 8) ? __expf(v1 - m) : 0.f);
#pragma unroll
    for (int o = 16; o > 0; o >>= 1) s += __shfl_xor_sync(0xffffffffu, s, o);
    float ls = m + __logf(s);

    out[(size_t)row * 40 + lane] = v0 - ls;
    if (lane < 8) out[(size_t)row * 40 + 32 + lane] = v1 - ls;
}

// ===========================================================================
extern "C" void kernel_launch(void* const* d_in, const int* in_sizes, int n_in,
                              void* d_out, int out_size) {
    const float* x    = (const float*)d_in[0];
    const int*   esrc = (const int*)  d_in[1];
    const int*   edst = (const int*)  d_in[2];
    const float* ew   = (const float*)d_in[3];
    const float* W1   = (const float*)d_in[4];
    const float* b1   = (const float*)d_in[5];
    const float* Wh   = (const float*)d_in[6];
    const float* bh   = (const float*)d_in[7];
    const float* W2   = (const float*)d_in[8];
    const float* b2   = (const float*)d_in[9];
    float* out = (float*)d_out;

    const int M  = in_sizes[0] / NFEAT;   // 50000
    const int nE = in_sizes[1];           // 1600000

    float *A, *B, *C;
    int *cnt, *cursor, *rp;
    int2 *pe;
    cudaGetSymbolAddress((void**)&A, g_A);
    cudaGetSymbolAddress((void**)&B, g_B);
    cudaGetSymbolAddress((void**)&C, g_C);
    cudaGetSymbolAddress((void**)&cnt, g_cnt);
    cudaGetSymbolAddress((void**)&cursor, g_cursor);
    cudaGetSymbolAddress((void**)&rp, g_rp);
    cudaGetSymbolAddress((void**)&pe, g_pe);

    cudaFuncSetAttribute(mma_gemm128, cudaFuncAttributeMaxDynamicSharedMemorySize,
                         SM_U32 * 4);

    // ---- CSR build (counting sort by dst) ----
    zero_int<<<(M + 255) / 256, 256>>>(cnt, M);
    hist_dst<<<(nE + 255) / 256, 256>>>(edst, cnt, nE);
    scan_rows<<<1, 1024>>>(cnt, rp, cursor, M);
    scatter_edges<<<(nE + 255) / 256, 256>>>(esrc, edst, ew, cursor, pe, nE);

    const int gemmBlocks = (M + 127) / 128;   // 391
    const int spmmBlocks = (M + 7) / 8;

    // Layer 1
    mma_gemm128<<<gemmBlocks, 256, SM_U32 * 4>>>(x, W1, A, M, NFEAT);
    spmm_csr128<<<spmmBlocks, 256>>>(A, rp, pe, b1, B, M);

    // Layer 2
    mma_gemm128<<<gemmBlocks, 256, SM_U32 * 4>>>(B, Wh, A, M, NHID);
    spmm_csr128<<<spmmBlocks, 256>>>(A, rp, pe, bh, B, M);

    // Layer 3 + log_softmax
    sgemm40<<<(M + 31) / 32, 256>>>(B, W2, C, M);
    spmm_csr40_lsm<<<spmmBlocks, 256>>>(C, rp, pe, b2, out, M);
}

// round 5
// speedup vs baseline: 5.7477x; 1.1327x over previous
#include <cuda_runtime.h>
#include <cuda_bf16.h>
#include <math.h>
#include <cstdint>

// ---------------------------------------------------------------------------
// GCN: 3x { H = A_sparse @ (H @ W) + b (,ReLU) } -> log_softmax
// N=50000, E=1.6M, 512 -> 128 -> 128 -> 40
// Round 5: HMMA bf16 hi/lo GEMM + CSR gather SpMM; CSR build overlapped with
//          layer-1 GEMM via stream fork/join inside graph capture; multi-block
//          scan; sgemm40 bank-conflict fix.
// ---------------------------------------------------------------------------

#define NNODES 50000
#define NEDGES 1600000
#define NFEAT 512
#define NHID  128
#define NCLASS 40
#define NB_SCAN 196   // ceil(50000/256)

// Scratch (__device__ globals; no allocations allowed)
__device__ float g_A[NNODES * NHID];
__device__ float g_B[NNODES * NHID];
__device__ float g_C[NNODES * NCLASS];
__device__ int   g_cnt[NNODES];
__device__ int   g_cursor[NNODES];
__device__ int   g_rp[NNODES + 1];
__device__ int   g_tmp[NNODES];         // per-element local exclusive scan
__device__ int   g_bsum[NB_SCAN];       // per-block sums
__device__ int   g_boff[NB_SCAN + 1];   // block offsets (+ grand total)
__device__ int2  g_pe[NEDGES];          // packed (src, weight-bits)

// ===========================================================================
// bf16 hi/lo helpers
// ===========================================================================
__device__ __forceinline__ void cvt_hilo(float x, float y, uint32_t& hi, uint32_t& lo) {
    __nv_bfloat16 hx = __float2bfloat16(x);
    __nv_bfloat16 hy = __float2bfloat16(y);
    float rx = x - __bfloat162float(hx);
    float ry = y - __bfloat162float(hy);
    __nv_bfloat162 H; H.x = hx; H.y = hy;
    __nv_bfloat162 L; L.x = __float2bfloat16(rx); L.y = __float2bfloat16(ry);
    hi = *reinterpret_cast<uint32_t*>(&H);
    lo = *reinterpret_cast<uint32_t*>(&L);
}

__device__ __forceinline__ void mma16816(float* d, const uint32_t* a, uint32_t b0, uint32_t b1) {
    asm volatile(
        "mma.sync.aligned.m16n8k16.row.col.f32.bf16.bf16.f32 "
        "{%0,%1,%2,%3}, {%4,%5,%6,%7}, {%8,%9}, {%0,%1,%2,%3};"
        : "+f"(d[0]), "+f"(d[1]), "+f"(d[2]), "+f"(d[3])
        : "r"(a[0]), "r"(a[1]), "r"(a[2]), "r"(a[3]), "r"(b0), "r"(b1));
}

// SMEM layout (u32 units). A tiles: [m=128][k2=32 + pad4]. B: [k2=32][n=128+8].
#define AH_OFF 0
#define AL_OFF 4608
#define BH_OFF 9216
#define BL_OFF 13568
#define SM_U32 17920   // 71680 bytes

// ===========================================================================
// mma.sync GEMM: C[M,128] = A[M,K] @ W[K,128], fp32 in/out, hi/lo bf16 split.
// ===========================================================================
__global__ void __launch_bounds__(256) mma_gemm128(
    const float* __restrict__ A, const float* __restrict__ W,
    float* __restrict__ C, int M, int K) {
    extern __shared__ uint32_t sm[];
    uint32_t* AH = sm + AH_OFF;
    uint32_t* AL = sm + AL_OFF;
    uint32_t* BH = sm + BH_OFF;
    uint32_t* BL = sm + BL_OFF;

    const int t = threadIdx.x;
    const int lane = t & 31;
    const int wid = t >> 5;
    const int warpM = wid >> 1;
    const int warpN = wid & 1;
    const int row0 = blockIdx.x * 128;

    float acc[2][8][4];
#pragma unroll
    for (int mt = 0; mt < 2; mt++)
#pragma unroll
        for (int nt = 0; nt < 8; nt++)
#pragma unroll
            for (int e = 0; e < 4; e++) acc[mt][nt][e] = 0.f;

    const int r4 = lane >> 2;
    const int q4 = lane & 3;

    const int nChunks = K >> 6;
    for (int c = 0; c < nChunks; c++) {
        const int k0 = c << 6;
        __syncthreads();

#pragma unroll
        for (int l = 0; l < 8; l++) {
            int q = t + l * 256;
            int m = q >> 4;
            int c4 = q & 15;
            float4 v = make_float4(0.f, 0.f, 0.f, 0.f);
            if (row0 + m < M)
                v = *reinterpret_cast<const float4*>(A + (size_t)(row0 + m) * K + k0 + c4 * 4);
            uint32_t h0, l0, h1, l1;
            cvt_hilo(v.x, v.y, h0, l0);
            cvt_hilo(v.z, v.w, h1, l1);
            int base = m * 36 + c4 * 2;
            AH[base] = h0; AH[base + 1] = h1;
            AL[base] = l0; AL[base + 1] = l1;
        }
#pragma unroll
        for (int l = 0; l < 16; l++) {
            int p = t + l * 256;
            int k2 = p >> 7;
            int n = p & 127;
            float v0 = __ldg(W + (size_t)(k0 + 2 * k2) * 128 + n);
            float v1 = __ldg(W + (size_t)(k0 + 2 * k2 + 1) * 128 + n);
            uint32_t h, lo;
            cvt_hilo(v0, v1, h, lo);
            BH[k2 * 136 + n] = h;
            BL[k2 * 136 + n] = lo;
        }
        __syncthreads();

#pragma unroll
        for (int k8 = 0; k8 < 4; k8++) {
            int klo = k8 * 8 + q4;
            uint32_t ah[2][4], al[2][4];
#pragma unroll
            for (int mt = 0; mt < 2; mt++) {
                int base = (warpM * 32 + mt * 16 + r4) * 36;
                ah[mt][0] = AH[base + klo];
                ah[mt][1] = AH[base + 8 * 36 + klo];
                ah[mt][2] = AH[base + klo + 4];
                ah[mt][3] = AH[base + 8 * 36 + klo + 4];
                al[mt][0] = AL[base + klo];
                al[mt][1] = AL[base + 8 * 36 + klo];
                al[mt][2] = AL[base + klo + 4];
                al[mt][3] = AL[base + 8 * 36 + klo + 4];
            }
#pragma unroll
            for (int nt = 0; nt < 8; nt++) {
                int nB = warpN * 64 + nt * 8 + r4;
                uint32_t bh0 = BH[klo * 136 + nB];
                uint32_t bh1 = BH[(klo + 4) * 136 + nB];
                uint32_t bl0 = BL[klo * 136 + nB];
                uint32_t bl1 = BL[(klo + 4) * 136 + nB];
#pragma unroll
                for (int mt = 0; mt < 2; mt++) {
                    mma16816(acc[mt][nt], ah[mt], bh0, bh1);
                    mma16816(acc[mt][nt], ah[mt], bl0, bl1);
                    mma16816(acc[mt][nt], al[mt], bh0, bh1);
                }
            }
        }
    }

#pragma unroll
    for (int mt = 0; mt < 2; mt++) {
        int rowA = row0 + warpM * 32 + mt * 16 + r4;
        int rowB = rowA + 8;
#pragma unroll
        for (int nt = 0; nt < 8; nt++) {
            int col = warpN * 64 + nt * 8 + q4 * 2;
            if (rowA < M)
                *reinterpret_cast<float2*>(C + (size_t)rowA * 128 + col) =
                    make_float2(acc[mt][nt][0], acc[mt][nt][1]);
            if (rowB < M)
                *reinterpret_cast<float2*>(C + (size_t)rowB * 128 + col) =
                    make_float2(acc[mt][nt][2], acc[mt][nt][3]);
        }
    }
}

// ===========================================================================
// CSR build: zero -> histogram -> 3-phase scan -> scatter
// ===========================================================================
__global__ void zero_int(int* p, int n) {
    int i = blockIdx.x * blockDim.x + threadIdx.x;
    if (i < n) p[i] = 0;
}

__global__ void hist_dst4(const int4* __restrict__ dst4, int* __restrict__ cnt, int n4) {
    int e = blockIdx.x * blockDim.x + threadIdx.x;
    if (e >= n4) return;
    int4 d = __ldg(dst4 + e);
    atomicAdd(&cnt[d.x], 1);
    atomicAdd(&cnt[d.y], 1);
    atomicAdd(&cnt[d.z], 1);
    atomicAdd(&cnt[d.w], 1);
}

// Generic 256-thread block exclusive scan step (device helper)
__device__ __forceinline__ int block_excl_scan(int v, int* wsum, int& total) {
    const int lane = threadIdx.x & 31;
    const int wid  = threadIdx.x >> 5;
    int incl = v;
#pragma unroll
    for (int o = 1; o < 32; o <<= 1) {
        int tt = __shfl_up_sync(0xffffffffu, incl, o);
        if (lane >= o) incl += tt;
    }
    if (lane == 31) wsum[wid] = incl;
    __syncthreads();
    if (wid == 0) {
        int s = (lane < 8) ? wsum[lane] : 0;
#pragma unroll
        for (int o = 1; o < 8; o <<= 1) {
            int tt = __shfl_up_sync(0xffffffffu, s, o);
            if (lane >= o) s += tt;
        }
        if (lane < 8) wsum[lane] = s;
    }
    __syncthreads();
    total = wsum[7];
    return (wid ? wsum[wid - 1] : 0) + incl - v;
}

__global__ void scan_p1(const int* __restrict__ cnt, int* __restrict__ tmp,
                        int* __restrict__ bsum, int n) {
    __shared__ int wsum[8];
    int i = blockIdx.x * 256 + threadIdx.x;
    int v = (i < n) ? cnt[i] : 0;
    int total;
    int excl = block_excl_scan(v, wsum, total);
    if (i < n) tmp[i] = excl;
    if (threadIdx.x == 0) bsum[blockIdx.x] = total;
}

__global__ void scan_p2(const int* __restrict__ bsum, int* __restrict__ boff, int nb) {
    __shared__ int wsum[8];
    int i = threadIdx.x;
    int v = (i < nb) ? bsum[i] : 0;
    int total;
    int excl = block_excl_scan(v, wsum, total);
    if (i <= nb) boff[i] = excl;   // boff[nb] == grand total
}

__global__ void scan_p3(const int* __restrict__ tmp, const int* __restrict__ boff,
                        int* __restrict__ rp, int* __restrict__ cursor, int n, int nb) {
    int i = blockIdx.x * 256 + threadIdx.x;
    if (i < n) {
        int v = tmp[i] + __ldg(boff + blockIdx.x);
        rp[i] = v;
        cursor[i] = v;
    }
    if (i == 0) rp[n] = __ldg(boff + nb);
}

__global__ void scatter_edges(const int* __restrict__ src, const int* __restrict__ dst,
                              const float* __restrict__ w, int* __restrict__ cursor,
                              int2* __restrict__ pe, int nE) {
    int e = blockIdx.x * blockDim.x + threadIdx.x;
    if (e >= nE) return;
    int d = dst[e];
    int pos = atomicAdd(&cursor[d], 1);
    pe[pos] = make_int2(src[e], __float_as_int(w[e]));
}

// ===========================================================================
// GEMM3: C[M,40] = H[M,128] @ W2[128,40]  (Ht padded: bank-conflict-free)
// ===========================================================================
__global__ void sgemm40(const float* __restrict__ H, const float* __restrict__ W,
                        float* __restrict__ C, int M) {
    __shared__ float Ht[32][132];
    __shared__ float Ws[128][40];

    const int t = threadIdx.x;
    const int row0 = blockIdx.x * 32;

#pragma unroll
    for (int l = 0; l < 4; l++) {
        int q = t + l * 256;
        int r = q >> 5;
        int c4 = q & 31;
        float4 v = make_float4(0.f, 0.f, 0.f, 0.f);
        if (row0 + r < M)
            v = *reinterpret_cast<const float4*>(H + (size_t)(row0 + r) * 128 + c4 * 4);
        *reinterpret_cast<float4*>(&Ht[r][c4 * 4]) = v;
    }
#pragma unroll
    for (int l = 0; l < 20; l++) {
        int q = t + l * 256;
        Ws[q / 40][q % 40] = W[q];
    }
    __syncthreads();

    const int r = t >> 3;
    const int cg = t & 7;
    float acc[5] = {0.f, 0.f, 0.f, 0.f, 0.f};
#pragma unroll 8
    for (int k = 0; k < 128; k++) {
        float h = Ht[r][k];
#pragma unroll
        for (int j = 0; j < 5; j++)
            acc[j] = fmaf(h, Ws[k][cg * 5 + j], acc[j]);
    }
    int grow = row0 + r;
    if (grow < M) {
#pragma unroll
        for (int j = 0; j < 5; j++)
            C[(size_t)grow * 40 + cg * 5 + j] = acc[j];
    }
}

// ===========================================================================
// Gather SpMM (feat=128) + bias + ReLU
// ===========================================================================
__global__ void __launch_bounds__(256) spmm_csr128(
    const float* __restrict__ H, const int* __restrict__ rp,
    const int2* __restrict__ pe, const float* __restrict__ bias,
    float* __restrict__ out, int M) {
    int row = blockIdx.x * 8 + (threadIdx.x >> 5);
    int lane = threadIdx.x & 31;
    if (row >= M) return;
    int p  = __ldg(rp + row);
    int pend = __ldg(rp + row + 1);

    const float* Hb = H + lane * 4;
    float ax = 0.f, ay = 0.f, az = 0.f, aw = 0.f;

    for (; p + 4 <= pend; p += 4) {
        int2 e0 = __ldg(pe + p + 0), e1 = __ldg(pe + p + 1);
        int2 e2 = __ldg(pe + p + 2), e3 = __ldg(pe + p + 3);
        float w0 = __int_as_float(e0.y), w1 = __int_as_float(e1.y);
        float w2 = __int_as_float(e2.y), w3 = __int_as_float(e3.y);
        float4 h0 = *reinterpret_cast<const float4*>(Hb + (size_t)e0.x * 128);
        float4 h1 = *reinterpret_cast<const float4*>(Hb + (size_t)e1.x * 128);
        float4 h2 = *reinterpret_cast<const float4*>(Hb + (size_t)e2.x * 128);
        float4 h3 = *reinterpret_cast<const float4*>(Hb + (size_t)e3.x * 128);
        ax = fmaf(w0, h0.x, ax); ay = fmaf(w0, h0.y, ay); az = fmaf(w0, h0.z, az); aw = fmaf(w0, h0.w, aw);
        ax = fmaf(w1, h1.x, ax); ay = fmaf(w1, h1.y, ay); az = fmaf(w1, h1.z, az); aw = fmaf(w1, h1.w, aw);
        ax = fmaf(w2, h2.x, ax); ay = fmaf(w2, h2.y, ay); az = fmaf(w2, h2.z, az); aw = fmaf(w2, h2.w, aw);
        ax = fmaf(w3, h3.x, ax); ay = fmaf(w3, h3.y, ay); az = fmaf(w3, h3.z, az); aw = fmaf(w3, h3.w, aw);
    }
    for (; p < pend; p++) {
        int2 e = __ldg(pe + p);
        float w = __int_as_float(e.y);
        float4 h = *reinterpret_cast<const float4*>(Hb + (size_t)e.x * 128);
        ax = fmaf(w, h.x, ax); ay = fmaf(w, h.y, ay); az = fmaf(w, h.z, az); aw = fmaf(w, h.w, aw);
    }

    float4 b4 = *reinterpret_cast<const float4*>(bias + lane * 4);
    float4 r4;
    r4.x = fmaxf(ax + b4.x, 0.f);
    r4.y = fmaxf(ay + b4.y, 0.f);
    r4.z = fmaxf(az + b4.z, 0.f);
    r4.w = fmaxf(aw + b4.w, 0.f);
    *reinterpret_cast<float4*>(out + (size_t)row * 128 + lane * 4) = r4;
}

// ===========================================================================
// Gather SpMM (feat=40) + bias + log_softmax
// ===========================================================================
__global__ void __launch_bounds__(256) spmm_csr40_lsm(
    const float* __restrict__ C, const int* __restrict__ rp,
    const int2* __restrict__ pe, const float* __restrict__ b,
    float* __restrict__ out, int M) {
    int row = blockIdx.x * 8 + (threadIdx.x >> 5);
    int lane = threadIdx.x & 31;
    if (row >= M) return;
    int p  = __ldg(rp + row);
    int pend = __ldg(rp + row + 1);

    float a0 = 0.f, a1 = 0.f;
    for (; p + 2 <= pend; p += 2) {
        int2 e0 = __ldg(pe + p), e1 = __ldg(pe + p + 1);
        float w0 = __int_as_float(e0.y), w1 = __int_as_float(e1.y);
        const float* c0 = C + (size_t)e0.x * 40;
        const float* c1 = C + (size_t)e1.x * 40;
        float x0 = __ldg(c0 + lane);
        float x1 = __ldg(c1 + lane);
        float y0 = (lane < 8) ? __ldg(c0 + 32 + lane) : 0.f;
        float y1 = (lane < 8) ? __ldg(c1 + 32 + lane) : 0.f;
        a0 = fmaf(w0, x0, a0); a0 = fmaf(w1, x1, a0);
        a1 = fmaf(w0, y0, a1); a1 = fmaf(w1, y1, a1);
    }
    if (p < pend) {
        int2 e = __ldg(pe + p);
        float w = __int_as_float(e.y);
        const float* c0 = C + (size_t)e.x * 40;
        a0 = fmaf(w, __ldg(c0 + lane), a0);
        if (lane < 8) a1 = fmaf(w, __ldg(c0 + 32 + lane), a1);
    }

    float v0 = a0 + __ldg(b + lane);
    float v1 = (lane < 8) ? (a1 + __ldg(b + 32 + lane)) : -INFINITY;

    float m = fmaxf(v0, v1);
#pragma unroll
    for (int o = 16; o > 0; o >>= 1) m = fmaxf(m, __shfl_xor_sync(0xffffffffu, m, o));
    float s = __expf(v0 - m) + ((lane < 8) ? __expf(v1 - m) : 0.f);
#pragma unroll
    for (int o = 16; o > 0; o >>= 1) s += __shfl_xor_sync(0xffffffffu, s, o);
    float ls = m + __logf(s);

    out[(size_t)row * 40 + lane] = v0 - ls;
    if (lane < 8) out[(size_t)row * 40 + 32 + lane] = v1 - ls;
}

// ===========================================================================
extern "C" void kernel_launch(void* const* d_in, const int* in_sizes, int n_in,
                              void* d_out, int out_size) {
    const float* x    = (const float*)d_in[0];
    const int*   esrc = (const int*)  d_in[1];
    const int*   edst = (const int*)  d_in[2];
    const float* ew   = (const float*)d_in[3];
    const float* W1   = (const float*)d_in[4];
    const float* b1   = (const float*)d_in[5];
    const float* Wh   = (const float*)d_in[6];
    const float* bh   = (const float*)d_in[7];
    const float* W2   = (const float*)d_in[8];
    const float* b2   = (const float*)d_in[9];
    float* out = (float*)d_out;

    const int M  = in_sizes[0] / NFEAT;   // 50000
    const int nE = in_sizes[1];           // 1600000

    float *A, *B, *C;
    int *cnt, *cursor, *rp, *tmp, *bsum, *boff;
    int2 *pe;
    cudaGetSymbolAddress((void**)&A, g_A);
    cudaGetSymbolAddress((void**)&B, g_B);
    cudaGetSymbolAddress((void**)&C, g_C);
    cudaGetSymbolAddress((void**)&cnt, g_cnt);
    cudaGetSymbolAddress((void**)&cursor, g_cursor);
    cudaGetSymbolAddress((void**)&rp, g_rp);
    cudaGetSymbolAddress((void**)&tmp, g_tmp);
    cudaGetSymbolAddress((void**)&bsum, g_bsum);
    cudaGetSymbolAddress((void**)&boff, g_boff);
    cudaGetSymbolAddress((void**)&pe, g_pe);

    static cudaStream_t s2 = nullptr;
    static cudaEvent_t evF = nullptr, evJ = nullptr;
    if (!s2) {
        cudaStreamCreateWithFlags(&s2, cudaStreamNonBlocking);
        cudaEventCreateWithFlags(&evF, cudaEventDisableTiming);
        cudaEventCreateWithFlags(&evJ, cudaEventDisableTiming);
        cudaFuncSetAttribute(mma_gemm128, cudaFuncAttributeMaxDynamicSharedMemorySize,
                             SM_U32 * 4);
    }

    const int nb = (M + 255) / 256;           // 196
    const int gemmBlocks = (M + 127) / 128;   // 391
    const int spmmBlocks = (M + 7) / 8;

    // ---- Fork: CSR build on s2, layer-1 GEMM on main stream ----
    cudaEventRecord(evF, 0);
    cudaStreamWaitEvent(s2, evF, 0);

    zero_int<<<nb, 256, 0, s2>>>(cnt, M);
    hist_dst4<<<((nE / 4) + 255) / 256, 256, 0, s2>>>((const int4*)edst, cnt, nE / 4);
    scan_p1<<<nb, 256, 0, s2>>>(cnt, tmp, bsum, M);
    scan_p2<<<1, 256, 0, s2>>>(bsum, boff, nb);
    scan_p3<<<nb, 256, 0, s2>>>(tmp, boff, rp, cursor, M, nb);
    scatter_edges<<<(nE + 255) / 256, 256, 0, s2>>>(esrc, edst, ew, cursor, pe, nE);
    cudaEventRecord(evJ, s2);

    mma_gemm128<<<gemmBlocks, 256, SM_U32 * 4>>>(x, W1, A, M, NFEAT);

    cudaStreamWaitEvent(0, evJ, 0);   // join

    // Layer 1 aggregation
    spmm_csr128<<<spmmBlocks, 256>>>(A, rp, pe, b1, B, M);

    // Layer 2
    mma_gemm128<<<gemmBlocks, 256, SM_U32 * 4>>>(B, Wh, A, M, NHID);
    spmm_csr128<<<spmmBlocks, 256>>>(A, rp, pe, bh, B, M);

    // Layer 3 + log_softmax
    sgemm40<<<(M + 31) / 32, 256>>>(B, W2, C, M);
    spmm_csr40_lsm<<<spmmBlocks, 256>>>(C, rp, pe, b2, out, M);
}

// round 6
// speedup vs baseline: 6.3324x; 1.1017x over previous
#include <cuda_runtime.h>
#include <cuda_bf16.h>
#include <cuda_fp16.h>
#include <math.h>
#include <cstdint>

// ---------------------------------------------------------------------------
// GCN: 3x { H = A_sparse @ (H @ W) + b (,ReLU) } -> log_softmax
// N=50000, E=1.6M, 512 -> 128 -> 128 -> 40
// Round 6: HMMA bf16 hi/lo GEMM writing fp16 (halves SpMM gather traffic,
//          which is at the L2 BW floor) + fp32-accumulating fp16 gather SpMM.
//          CSR build overlapped with layer-1 GEMM. Logits path stays fp32.
// ---------------------------------------------------------------------------

#define NNODES 50000
#define NEDGES 1600000
#define NFEAT 512
#define NHID  128
#define NCLASS 40
#define NB_SCAN 196   // ceil(50000/256)

// Scratch (__device__ globals; no allocations allowed)
__device__ __half g_Ah[NNODES * NHID];  // GEMM output (fp16) / SpMM input
__device__ float g_B[NNODES * NHID];    // SpMM output / next GEMM input
__device__ float g_C[NNODES * NCLASS];  // GEMM3 output (fp32: final layer)
__device__ int   g_cnt[NNODES];
__device__ int   g_cursor[NNODES];
__device__ int   g_rp[NNODES + 1];
__device__ int   g_tmp[NNODES];
__device__ int   g_bsum[NB_SCAN];
__device__ int   g_boff[NB_SCAN + 1];
__device__ int2  g_pe[NEDGES];          // packed (src, weight-bits)

// ===========================================================================
// bf16 hi/lo helpers
// ===========================================================================
__device__ __forceinline__ void cvt_hilo(float x, float y, uint32_t& hi, uint32_t& lo) {
    __nv_bfloat16 hx = __float2bfloat16(x);
    __nv_bfloat16 hy = __float2bfloat16(y);
    float rx = x - __bfloat162float(hx);
    float ry = y - __bfloat162float(hy);
    __nv_bfloat162 H; H.x = hx; H.y = hy;
    __nv_bfloat162 L; L.x = __float2bfloat16(rx); L.y = __float2bfloat16(ry);
    hi = *reinterpret_cast<uint32_t*>(&H);
    lo = *reinterpret_cast<uint32_t*>(&L);
}

__device__ __forceinline__ void mma16816(float* d, const uint32_t* a, uint32_t b0, uint32_t b1) {
    asm volatile(
        "mma.sync.aligned.m16n8k16.row.col.f32.bf16.bf16.f32 "
        "{%0,%1,%2,%3}, {%4,%5,%6,%7}, {%8,%9}, {%0,%1,%2,%3};"
        : "+f"(d[0]), "+f"(d[1]), "+f"(d[2]), "+f"(d[3])
        : "r"(a[0]), "r"(a[1]), "r"(a[2]), "r"(a[3]), "r"(b0), "r"(b1));
}

// SMEM layout (u32 units). A tiles: [m=128][k2=32 + pad4]. B: [k2=32][n=128+8].
#define AH_OFF 0
#define AL_OFF 4608
#define BH_OFF 9216
#define BL_OFF 13568
#define SM_U32 17920   // 71680 bytes

// ===========================================================================
// mma.sync GEMM: C[M,128] = A[M,K] @ W[K,128], fp32 in, fp16 out, hi/lo split.
// ===========================================================================
__global__ void __launch_bounds__(256) mma_gemm128(
    const float* __restrict__ A, const float* __restrict__ W,
    __half* __restrict__ C, int M, int K) {
    extern __shared__ uint32_t sm[];
    uint32_t* AH = sm + AH_OFF;
    uint32_t* AL = sm + AL_OFF;
    uint32_t* BH = sm + BH_OFF;
    uint32_t* BL = sm + BL_OFF;

    const int t = threadIdx.x;
    const int lane = t & 31;
    const int wid = t >> 5;
    const int warpM = wid >> 1;
    const int warpN = wid & 1;
    const int row0 = blockIdx.x * 128;

    float acc[2][8][4];
#pragma unroll
    for (int mt = 0; mt < 2; mt++)
#pragma unroll
        for (int nt = 0; nt < 8; nt++)
#pragma unroll
            for (int e = 0; e < 4; e++) acc[mt][nt][e] = 0.f;

    const int r4 = lane >> 2;
    const int q4 = lane & 3;

    const int nChunks = K >> 6;
    for (int c = 0; c < nChunks; c++) {
        const int k0 = c << 6;
        __syncthreads();

#pragma unroll
        for (int l = 0; l < 8; l++) {
            int q = t + l * 256;
            int m = q >> 4;
            int c4 = q & 15;
            float4 v = make_float4(0.f, 0.f, 0.f, 0.f);
            if (row0 + m < M)
                v = *reinterpret_cast<const float4*>(A + (size_t)(row0 + m) * K + k0 + c4 * 4);
            uint32_t h0, l0, h1, l1;
            cvt_hilo(v.x, v.y, h0, l0);
            cvt_hilo(v.z, v.w, h1, l1);
            int base = m * 36 + c4 * 2;
            AH[base] = h0; AH[base + 1] = h1;
            AL[base] = l0; AL[base + 1] = l1;
        }
#pragma unroll
        for (int l = 0; l < 16; l++) {
            int p = t + l * 256;
            int k2 = p >> 7;
            int n = p & 127;
            float v0 = __ldg(W + (size_t)(k0 + 2 * k2) * 128 + n);
            float v1 = __ldg(W + (size_t)(k0 + 2 * k2 + 1) * 128 + n);
            uint32_t h, lo;
            cvt_hilo(v0, v1, h, lo);
            BH[k2 * 136 + n] = h;
            BL[k2 * 136 + n] = lo;
        }
        __syncthreads();

#pragma unroll
        for (int k8 = 0; k8 < 4; k8++) {
            int klo = k8 * 8 + q4;
            uint32_t ah[2][4], al[2][4];
#pragma unroll
            for (int mt = 0; mt < 2; mt++) {
                int base = (warpM * 32 + mt * 16 + r4) * 36;
                ah[mt][0] = AH[base + klo];
                ah[mt][1] = AH[base + 8 * 36 + klo];
                ah[mt][2] = AH[base + klo + 4];
                ah[mt][3] = AH[base + 8 * 36 + klo + 4];
                al[mt][0] = AL[base + klo];
                al[mt][1] = AL[base + 8 * 36 + klo];
                al[mt][2] = AL[base + klo + 4];
                al[mt][3] = AL[base + 8 * 36 + klo + 4];
            }
#pragma unroll
            for (int nt = 0; nt < 8; nt++) {
                int nB = warpN * 64 + nt * 8 + r4;
                uint32_t bh0 = BH[klo * 136 + nB];
                uint32_t bh1 = BH[(klo + 4) * 136 + nB];
                uint32_t bl0 = BL[klo * 136 + nB];
                uint32_t bl1 = BL[(klo + 4) * 136 + nB];
#pragma unroll
                for (int mt = 0; mt < 2; mt++) {
                    mma16816(acc[mt][nt], ah[mt], bh0, bh1);
                    mma16816(acc[mt][nt], ah[mt], bl0, bl1);
                    mma16816(acc[mt][nt], al[mt], bh0, bh1);
                }
            }
        }
    }

    // ---- epilogue: write fp16 (half2 per pair) ----
#pragma unroll
    for (int mt = 0; mt < 2; mt++) {
        int rowA = row0 + warpM * 32 + mt * 16 + r4;
        int rowB = rowA + 8;
#pragma unroll
        for (int nt = 0; nt < 8; nt++) {
            int col = warpN * 64 + nt * 8 + q4 * 2;
            if (rowA < M)
                *reinterpret_cast<__half2*>(C + (size_t)rowA * 128 + col) =
                    __floats2half2_rn(acc[mt][nt][0], acc[mt][nt][1]);
            if (rowB < M)
                *reinterpret_cast<__half2*>(C + (size_t)rowB * 128 + col) =
                    __floats2half2_rn(acc[mt][nt][2], acc[mt][nt][3]);
        }
    }
}

// ===========================================================================
// CSR build: zero -> histogram -> 3-phase scan -> scatter
// ===========================================================================
__global__ void zero_int(int* p, int n) {
    int i = blockIdx.x * blockDim.x + threadIdx.x;
    if (i < n) p[i] = 0;
}

__global__ void hist_dst4(const int4* __restrict__ dst4, int* __restrict__ cnt, int n4) {
    int e = blockIdx.x * blockDim.x + threadIdx.x;
    if (e >= n4) return;
    int4 d = __ldg(dst4 + e);
    atomicAdd(&cnt[d.x], 1);
    atomicAdd(&cnt[d.y], 1);
    atomicAdd(&cnt[d.z], 1);
    atomicAdd(&cnt[d.w], 1);
}

__device__ __forceinline__ int block_excl_scan(int v, int* wsum, int& total) {
    const int lane = threadIdx.x & 31;
    const int wid  = threadIdx.x >> 5;
    int incl = v;
#pragma unroll
    for (int o = 1; o < 32; o <<= 1) {
        int tt = __shfl_up_sync(0xffffffffu, incl, o);
        if (lane >= o) incl += tt;
    }
    if (lane == 31) wsum[wid] = incl;
    __syncthreads();
    if (wid == 0) {
        int s = (lane < 8) ? wsum[lane] : 0;
#pragma unroll
        for (int o = 1; o < 8; o <<= 1) {
            int tt = __shfl_up_sync(0xffffffffu, s, o);
            if (lane >= o) s += tt;
        }
        if (lane < 8) wsum[lane] = s;
    }
    __syncthreads();
    total = wsum[7];
    return (wid ? wsum[wid - 1] : 0) + incl - v;
}

__global__ void scan_p1(const int* __restrict__ cnt, int* __restrict__ tmp,
                        int* __restrict__ bsum, int n) {
    __shared__ int wsum[8];
    int i = blockIdx.x * 256 + threadIdx.x;
    int v = (i < n) ? cnt[i] : 0;
    int total;
    int excl = block_excl_scan(v, wsum, total);
    if (i < n) tmp[i] = excl;
    if (threadIdx.x == 0) bsum[blockIdx.x] = total;
}

__global__ void scan_p2(const int* __restrict__ bsum, int* __restrict__ boff, int nb) {
    __shared__ int wsum[8];
    int i = threadIdx.x;
    int v = (i < nb) ? bsum[i] : 0;
    int total;
    int excl = block_excl_scan(v, wsum, total);
    if (i <= nb) boff[i] = excl;
}

__global__ void scan_p3(const int* __restrict__ tmp, const int* __restrict__ boff,
                        int* __restrict__ rp, int* __restrict__ cursor, int n, int nb) {
    int i = blockIdx.x * 256 + threadIdx.x;
    if (i < n) {
        int v = tmp[i] + __ldg(boff + blockIdx.x);
        rp[i] = v;
        cursor[i] = v;
    }
    if (i == 0) rp[n] = __ldg(boff + nb);
}

__global__ void scatter_edges(const int* __restrict__ src, const int* __restrict__ dst,
                              const float* __restrict__ w, int* __restrict__ cursor,
                              int2* __restrict__ pe, int nE) {
    int e = blockIdx.x * blockDim.x + threadIdx.x;
    if (e >= nE) return;
    int d = dst[e];
    int pos = atomicAdd(&cursor[d], 1);
    pe[pos] = make_int2(src[e], __float_as_int(w[e]));
}

// ===========================================================================
// GEMM3: C[M,40] = H[M,128] @ W2[128,40]  (fp32 all the way: final layer)
// ===========================================================================
__global__ void sgemm40(const float* __restrict__ H, const float* __restrict__ W,
                        float* __restrict__ C, int M) {
    __shared__ float Ht[32][132];
    __shared__ float Ws[128][40];

    const int t = threadIdx.x;
    const int row0 = blockIdx.x * 32;

#pragma unroll
    for (int l = 0; l < 4; l++) {
        int q = t + l * 256;
        int r = q >> 5;
        int c4 = q & 31;
        float4 v = make_float4(0.f, 0.f, 0.f, 0.f);
        if (row0 + r < M)
            v = *reinterpret_cast<const float4*>(H + (size_t)(row0 + r) * 128 + c4 * 4);
        *reinterpret_cast<float4*>(&Ht[r][c4 * 4]) = v;
    }
#pragma unroll
    for (int l = 0; l < 20; l++) {
        int q = t + l * 256;
        Ws[q / 40][q % 40] = W[q];
    }
    __syncthreads();

    const int r = t >> 3;
    const int cg = t & 7;
    float acc[5] = {0.f, 0.f, 0.f, 0.f, 0.f};
#pragma unroll 8
    for (int k = 0; k < 128; k++) {
        float h = Ht[r][k];
#pragma unroll
        for (int j = 0; j < 5; j++)
            acc[j] = fmaf(h, Ws[k][cg * 5 + j], acc[j]);
    }
    int grow = row0 + r;
    if (grow < M) {
#pragma unroll
        for (int j = 0; j < 5; j++)
            C[(size_t)grow * 40 + cg * 5 + j] = acc[j];
    }
}

// ===========================================================================
// Gather SpMM (feat=128, fp16 input, fp32 accumulate) + bias + ReLU
// One warp per dst row; lane owns 4 features (one uint2 = 4 fp16 per edge).
// ===========================================================================
__global__ void __launch_bounds__(256) spmm_csr128h(
    const __half* __restrict__ H, const int* __restrict__ rp,
    const int2* __restrict__ pe, const float* __restrict__ bias,
    float* __restrict__ out, int M) {
    int row = blockIdx.x * 8 + (threadIdx.x >> 5);
    int lane = threadIdx.x & 31;
    if (row >= M) return;
    int p  = __ldg(rp + row);
    int pend = __ldg(rp + row + 1);

    const char* Hb = reinterpret_cast<const char*>(H) + lane * 8;  // 4 fp16 per lane
    float ax = 0.f, ay = 0.f, az = 0.f, aw = 0.f;

    for (; p + 4 <= pend; p += 4) {
        int2 e0 = __ldg(pe + p + 0), e1 = __ldg(pe + p + 1);
        int2 e2 = __ldg(pe + p + 2), e3 = __ldg(pe + p + 3);
        float w0 = __int_as_float(e0.y), w1 = __int_as_float(e1.y);
        float w2 = __int_as_float(e2.y), w3 = __int_as_float(e3.y);
        uint2 r0 = *reinterpret_cast<const uint2*>(Hb + (size_t)e0.x * 256);
        uint2 r1 = *reinterpret_cast<const uint2*>(Hb + (size_t)e1.x * 256);
        uint2 r2 = *reinterpret_cast<const uint2*>(Hb + (size_t)e2.x * 256);
        uint2 r3 = *reinterpret_cast<const uint2*>(Hb + (size_t)e3.x * 256);
        float2 a01, a23;
        a01 = __half22float2(*reinterpret_cast<__half2*>(&r0.x));
        a23 = __half22float2(*reinterpret_cast<__half2*>(&r0.y));
        ax = fmaf(w0, a01.x, ax); ay = fmaf(w0, a01.y, ay);
        az = fmaf(w0, a23.x, az); aw = fmaf(w0, a23.y, aw);
        a01 = __half22float2(*reinterpret_cast<__half2*>(&r1.x));
        a23 = __half22float2(*reinterpret_cast<__half2*>(&r1.y));
        ax = fmaf(w1, a01.x, ax); ay = fmaf(w1, a01.y, ay);
        az = fmaf(w1, a23.x, az); aw = fmaf(w1, a23.y, aw);
        a01 = __half22float2(*reinterpret_cast<__half2*>(&r2.x));
        a23 = __half22float2(*reinterpret_cast<__half2*>(&r2.y));
        ax = fmaf(w2, a01.x, ax); ay = fmaf(w2, a01.y, ay);
        az = fmaf(w2, a23.x, az); aw = fmaf(w2, a23.y, aw);
        a01 = __half22float2(*reinterpret_cast<__half2*>(&r3.x));
        a23 = __half22float2(*reinterpret_cast<__half2*>(&r3.y));
        ax = fmaf(w3, a01.x, ax); ay = fmaf(w3, a01.y, ay);
        az = fmaf(w3, a23.x, az); aw = fmaf(w3, a23.y, aw);
    }
    for (; p < pend; p++) {
        int2 e = __ldg(pe + p);
        float w = __int_as_float(e.y);
        uint2 r0 = *reinterpret_cast<const uint2*>(Hb + (size_t)e.x * 256);
        float2 a01 = __half22float2(*reinterpret_cast<__half2*>(&r0.x));
        float2 a23 = __half22float2(*reinterpret_cast<__half2*>(&r0.y));
        ax = fmaf(w, a01.x, ax); ay = fmaf(w, a01.y, ay);
        az = fmaf(w, a23.x, az); aw = fmaf(w, a23.y, aw);
    }

    float4 b4 = *reinterpret_cast<const float4*>(bias + lane * 4);
    float4 r4;
    r4.x = fmaxf(ax + b4.x, 0.f);
    r4.y = fmaxf(ay + b4.y, 0.f);
    r4.z = fmaxf(az + b4.z, 0.f);
    r4.w = fmaxf(aw + b4.w, 0.f);
    *reinterpret_cast<float4*>(out + (size_t)row * 128 + lane * 4) = r4;
}

// ===========================================================================
// Gather SpMM (feat=40, fp32) + bias + log_softmax
// ===========================================================================
__global__ void __launch_bounds__(256) spmm_csr40_lsm(
    const float* __restrict__ C, const int* __restrict__ rp,
    const int2* __restrict__ pe, const float* __restrict__ b,
    float* __restrict__ out, int M) {
    int row = blockIdx.x * 8 + (threadIdx.x >> 5);
    int lane = threadIdx.x & 31;
    if (row >= M) return;
    int p  = __ldg(rp + row);
    int pend = __ldg(rp + row + 1);

    float a0 = 0.f, a1 = 0.f;
    for (; p + 2 <= pend; p += 2) {
        int2 e0 = __ldg(pe + p), e1 = __ldg(pe + p + 1);
        float w0 = __int_as_float(e0.y), w1 = __int_as_float(e1.y);
        const float* c0 = C + (size_t)e0.x * 40;
        const float* c1 = C + (size_t)e1.x * 40;
        float x0 = __ldg(c0 + lane);
        float x1 = __ldg(c1 + lane);
        float y0 = (lane < 8) ? __ldg(c0 + 32 + lane) : 0.f;
        float y1 = (lane < 8) ? __ldg(c1 + 32 + lane) : 0.f;
        a0 = fmaf(w0, x0, a0); a0 = fmaf(w1, x1, a0);
        a1 = fmaf(w0, y0, a1); a1 = fmaf(w1, y1, a1);
    }
    if (p < pend) {
        int2 e = __ldg(pe + p);
        float w = __int_as_float(e.y);
        const float* c0 = C + (size_t)e.x * 40;
        a0 = fmaf(w, __ldg(c0 + lane), a0);
        if (lane < 8) a1 = fmaf(w, __ldg(c0 + 32 + lane), a1);
    }

    float v0 = a0 + __ldg(b + lane);
    float v1 = (lane < 8) ? (a1 + __ldg(b + 32 + lane)) : -INFINITY;

    float m = fmaxf(v0, v1);
#pragma unroll
    for (int o = 16; o > 0; o >>= 1) m = fmaxf(m, __shfl_xor_sync(0xffffffffu, m, o));
    float s = __expf(v0 - m) + ((lane < 8) ? __expf(v1 - m) : 0.f);
#pragma unroll
    for (int o = 16; o > 0; o >>= 1) s += __shfl_xor_sync(0xffffffffu, s, o);
    float ls = m + __logf(s);

    out[(size_t)row * 40 + lane] = v0 - ls;
    if (lane < 8) out[(size_t)row * 40 + 32 + lane] = v1 - ls;
}

// ===========================================================================
extern "C" void kernel_launch(void* const* d_in, const int* in_sizes, int n_in,
                              void* d_out, int out_size) {
    const float* x    = (const float*)d_in[0];
    const int*   esrc = (const int*)  d_in[1];
    const int*   edst = (const int*)  d_in[2];
    const float* ew   = (const float*)d_in[3];
    const float* W1   = (const float*)d_in[4];
    const float* b1   = (const float*)d_in[5];
    const float* Wh   = (const float*)d_in[6];
    const float* bh   = (const float*)d_in[7];
    const float* W2   = (const float*)d_in[8];
    const float* b2   = (const float*)d_in[9];
    float* out = (float*)d_out;

    const int M  = in_sizes[0] / NFEAT;   // 50000
    const int nE = in_sizes[1];           // 1600000

    __half* Ah;
    float *B, *C;
    int *cnt, *cursor, *rp, *tmp, *bsum, *boff;
    int2 *pe;
    cudaGetSymbolAddress((void**)&Ah, g_Ah);
    cudaGetSymbolAddress((void**)&B, g_B);
    cudaGetSymbolAddress((void**)&C, g_C);
    cudaGetSymbolAddress((void**)&cnt, g_cnt);
    cudaGetSymbolAddress((void**)&cursor, g_cursor);
    cudaGetSymbolAddress((void**)&rp, g_rp);
    cudaGetSymbolAddress((void**)&tmp, g_tmp);
    cudaGetSymbolAddress((void**)&bsum, g_bsum);
    cudaGetSymbolAddress((void**)&boff, g_boff);
    cudaGetSymbolAddress((void**)&pe, g_pe);

    static cudaStream_t s2 = nullptr;
    static cudaEvent_t evF = nullptr, evJ = nullptr;
    if (!s2) {
        cudaStreamCreateWithFlags(&s2, cudaStreamNonBlocking);
        cudaEventCreateWithFlags(&evF, cudaEventDisableTiming);
        cudaEventCreateWithFlags(&evJ, cudaEventDisableTiming);
        cudaFuncSetAttribute(mma_gemm128, cudaFuncAttributeMaxDynamicSharedMemorySize,
                             SM_U32 * 4);
    }

    const int nb = (M + 255) / 256;           // 196
    const int gemmBlocks = (M + 127) / 128;   // 391
    const int spmmBlocks = (M + 7) / 8;

    // ---- Fork: CSR build on s2, layer-1 GEMM on main stream ----
    cudaEventRecord(evF, 0);
    cudaStreamWaitEvent(s2, evF, 0);

    zero_int<<<nb, 256, 0, s2>>>(cnt, M);
    hist_dst4<<<((nE / 4) + 255) / 256, 256, 0, s2>>>((const int4*)edst, cnt, nE / 4);
    scan_p1<<<nb, 256, 0, s2>>>(cnt, tmp, bsum, M);
    scan_p2<<<1, 256, 0, s2>>>(bsum, boff, nb);
    scan_p3<<<nb, 256, 0, s2>>>(tmp, boff, rp, cursor, M, nb);
    scatter_edges<<<(nE + 255) / 256, 256, 0, s2>>>(esrc, edst, ew, cursor, pe, nE);
    cudaEventRecord(evJ, s2);

    mma_gemm128<<<gemmBlocks, 256, SM_U32 * 4>>>(x, W1, Ah, M, NFEAT);

    cudaStreamWaitEvent(0, evJ, 0);   // join

    // Layer 1 aggregation
    spmm_csr128h<<<spmmBlocks, 256>>>(Ah, rp, pe, b1, B, M);

    // Layer 2
    mma_gemm128<<<gemmBlocks, 256, SM_U32 * 4>>>(B, Wh, Ah, M, NHID);
    spmm_csr128h<<<spmmBlocks, 256>>>(Ah, rp, pe, bh, B, M);

    // Layer 3 + log_softmax
    sgemm40<<<(M + 31) / 32, 256>>>(B, W2, C, M);
    spmm_csr40_lsm<<<spmmBlocks, 256>>>(C, rp, pe, b2, out, M);
}

// round 7
// speedup vs baseline: 6.3602x; 1.0044x over previous
#include <cuda_runtime.h>
#include <cuda_bf16.h>
#include <cuda_fp16.h>
#include <math.h>
#include <cstdint>

// ---------------------------------------------------------------------------
// GCN: 3x { H = A_sparse @ (H @ W) + b (,ReLU) } -> log_softmax
// N=50000, E=1.6M, 512 -> 128 -> 128 -> 40
// Round 7: fp16 logits gather (layer 3), vectorized CSR build, spmm unroll 8.
// ---------------------------------------------------------------------------

#define NNODES 50000
#define NEDGES 1600000
#define NFEAT 512
#define NHID  128
#define NCLASS 40
#define NB_SCAN 196   // ceil(50000/256)

// Scratch (__device__ globals; no allocations allowed)
__device__ __half g_Ah[NNODES * NHID];   // GEMM output (fp16) / SpMM input
__device__ float  g_B[NNODES * NHID];    // SpMM output / next GEMM input
__device__ __half g_Ch[NNODES * NCLASS]; // GEMM3 output (fp16 logits)
__device__ int    g_cnt[NNODES];
__device__ int    g_cursor[NNODES];
__device__ int    g_rp[NNODES + 1];
__device__ int    g_tmp[NNODES];
__device__ int    g_bsum[NB_SCAN];
__device__ int    g_boff[NB_SCAN + 1];
__device__ int2   g_pe[NEDGES];          // packed (src, weight-bits)

// ===========================================================================
// bf16 hi/lo helpers
// ===========================================================================
__device__ __forceinline__ void cvt_hilo(float x, float y, uint32_t& hi, uint32_t& lo) {
    __nv_bfloat16 hx = __float2bfloat16(x);
    __nv_bfloat16 hy = __float2bfloat16(y);
    float rx = x - __bfloat162float(hx);
    float ry = y - __bfloat162float(hy);
    __nv_bfloat162 H; H.x = hx; H.y = hy;
    __nv_bfloat162 L; L.x = __float2bfloat16(rx); L.y = __float2bfloat16(ry);
    hi = *reinterpret_cast<uint32_t*>(&H);
    lo = *reinterpret_cast<uint32_t*>(&L);
}

__device__ __forceinline__ void mma16816(float* d, const uint32_t* a, uint32_t b0, uint32_t b1) {
    asm volatile(
        "mma.sync.aligned.m16n8k16.row.col.f32.bf16.bf16.f32 "
        "{%0,%1,%2,%3}, {%4,%5,%6,%7}, {%8,%9}, {%0,%1,%2,%3};"
        : "+f"(d[0]), "+f"(d[1]), "+f"(d[2]), "+f"(d[3])
        : "r"(a[0]), "r"(a[1]), "r"(a[2]), "r"(a[3]), "r"(b0), "r"(b1));
}

// SMEM layout (u32 units). A tiles: [m=128][k2=32 + pad4]. B: [k2=32][n=128+8].
#define AH_OFF 0
#define AL_OFF 4608
#define BH_OFF 9216
#define BL_OFF 13568
#define SM_U32 17920   // 71680 bytes

// ===========================================================================
// mma.sync GEMM: C[M,128] = A[M,K] @ W[K,128], fp32 in, fp16 out, hi/lo split.
// ===========================================================================
__global__ void __launch_bounds__(256) mma_gemm128(
    const float* __restrict__ A, const float* __restrict__ W,
    __half* __restrict__ C, int M, int K) {
    extern __shared__ uint32_t sm[];
    uint32_t* AH = sm + AH_OFF;
    uint32_t* AL = sm + AL_OFF;
    uint32_t* BH = sm + BH_OFF;
    uint32_t* BL = sm + BL_OFF;

    const int t = threadIdx.x;
    const int lane = t & 31;
    const int wid = t >> 5;
    const int warpM = wid >> 1;
    const int warpN = wid & 1;
    const int row0 = blockIdx.x * 128;

    float acc[2][8][4];
#pragma unroll
    for (int mt = 0; mt < 2; mt++)
#pragma unroll
        for (int nt = 0; nt < 8; nt++)
#pragma unroll
            for (int e = 0; e < 4; e++) acc[mt][nt][e] = 0.f;

    const int r4 = lane >> 2;
    const int q4 = lane & 3;

    const int nChunks = K >> 6;
    for (int c = 0; c < nChunks; c++) {
        const int k0 = c << 6;
        __syncthreads();

#pragma unroll
        for (int l = 0; l < 8; l++) {
            int q = t + l * 256;
            int m = q >> 4;
            int c4 = q & 15;
            float4 v = make_float4(0.f, 0.f, 0.f, 0.f);
            if (row0 + m < M)
                v = *reinterpret_cast<const float4*>(A + (size_t)(row0 + m) * K + k0 + c4 * 4);
            uint32_t h0, l0, h1, l1;
            cvt_hilo(v.x, v.y, h0, l0);
            cvt_hilo(v.z, v.w, h1, l1);
            int base = m * 36 + c4 * 2;
            AH[base] = h0; AH[base + 1] = h1;
            AL[base] = l0; AL[base + 1] = l1;
        }
#pragma unroll
        for (int l = 0; l < 16; l++) {
            int p = t + l * 256;
            int k2 = p >> 7;
            int n = p & 127;
            float v0 = __ldg(W + (size_t)(k0 + 2 * k2) * 128 + n);
            float v1 = __ldg(W + (size_t)(k0 + 2 * k2 + 1) * 128 + n);
            uint32_t h, lo;
            cvt_hilo(v0, v1, h, lo);
            BH[k2 * 136 + n] = h;
            BL[k2 * 136 + n] = lo;
        }
        __syncthreads();

#pragma unroll
        for (int k8 = 0; k8 < 4; k8++) {
            int klo = k8 * 8 + q4;
            uint32_t ah[2][4], al[2][4];
#pragma unroll
            for (int mt = 0; mt < 2; mt++) {
                int base = (warpM * 32 + mt * 16 + r4) * 36;
                ah[mt][0] = AH[base + klo];
                ah[mt][1] = AH[base + 8 * 36 + klo];
                ah[mt][2] = AH[base + klo + 4];
                ah[mt][3] = AH[base + 8 * 36 + klo + 4];
                al[mt][0] = AL[base + klo];
                al[mt][1] = AL[base + 8 * 36 + klo];
                al[mt][2] = AL[base + klo + 4];
                al[mt][3] = AL[base + 8 * 36 + klo + 4];
            }
#pragma unroll
            for (int nt = 0; nt < 8; nt++) {
                int nB = warpN * 64 + nt * 8 + r4;
                uint32_t bh0 = BH[klo * 136 + nB];
                uint32_t bh1 = BH[(klo + 4) * 136 + nB];
                uint32_t bl0 = BL[klo * 136 + nB];
                uint32_t bl1 = BL[(klo + 4) * 136 + nB];
#pragma unroll
                for (int mt = 0; mt < 2; mt++) {
                    mma16816(acc[mt][nt], ah[mt], bh0, bh1);
                    mma16816(acc[mt][nt], ah[mt], bl0, bl1);
                    mma16816(acc[mt][nt], al[mt], bh0, bh1);
                }
            }
        }
    }

    // ---- epilogue: write fp16 (half2 per pair) ----
#pragma unroll
    for (int mt = 0; mt < 2; mt++) {
        int rowA = row0 + warpM * 32 + mt * 16 + r4;
        int rowB = rowA + 8;
#pragma unroll
        for (int nt = 0; nt < 8; nt++) {
            int col = warpN * 64 + nt * 8 + q4 * 2;
            if (rowA < M)
                *reinterpret_cast<__half2*>(C + (size_t)rowA * 128 + col) =
                    __floats2half2_rn(acc[mt][nt][0], acc[mt][nt][1]);
            if (rowB < M)
                *reinterpret_cast<__half2*>(C + (size_t)rowB * 128 + col) =
                    __floats2half2_rn(acc[mt][nt][2], acc[mt][nt][3]);
        }
    }
}

// ===========================================================================
// CSR build: zero -> histogram -> 3-phase scan -> scatter (vectorized)
// ===========================================================================
__global__ void zero_int4(int4* p, int n4) {
    int i = blockIdx.x * blockDim.x + threadIdx.x;
    if (i < n4) p[i] = make_int4(0, 0, 0, 0);
}

__global__ void hist_dst4(const int4* __restrict__ dst4, int* __restrict__ cnt, int n4) {
    int e = blockIdx.x * blockDim.x + threadIdx.x;
    if (e >= n4) return;
    int4 d = __ldg(dst4 + e);
    atomicAdd(&cnt[d.x], 1);
    atomicAdd(&cnt[d.y], 1);
    atomicAdd(&cnt[d.z], 1);
    atomicAdd(&cnt[d.w], 1);
}

__device__ __forceinline__ int block_excl_scan(int v, int* wsum, int& total) {
    const int lane = threadIdx.x & 31;
    const int wid  = threadIdx.x >> 5;
    int incl = v;
#pragma unroll
    for (int o = 1; o < 32; o <<= 1) {
        int tt = __shfl_up_sync(0xffffffffu, incl, o);
        if (lane >= o) incl += tt;
    }
    if (lane == 31) wsum[wid] = incl;
    __syncthreads();
    if (wid == 0) {
        int s = (lane < 8) ? wsum[lane] : 0;
#pragma unroll
        for (int o = 1; o < 8; o <<= 1) {
            int tt = __shfl_up_sync(0xffffffffu, s, o);
            if (lane >= o) s += tt;
        }
        if (lane < 8) wsum[lane] = s;
    }
    __syncthreads();
    total = wsum[7];
    return (wid ? wsum[wid - 1] : 0) + incl - v;
}

__global__ void scan_p1(const int* __restrict__ cnt, int* __restrict__ tmp,
                        int* __restrict__ bsum, int n) {
    __shared__ int wsum[8];
    int i = blockIdx.x * 256 + threadIdx.x;
    int v = (i < n) ? cnt[i] : 0;
    int total;
    int excl = block_excl_scan(v, wsum, total);
    if (i < n) tmp[i] = excl;
    if (threadIdx.x == 0) bsum[blockIdx.x] = total;
}

__global__ void scan_p2(const int* __restrict__ bsum, int* __restrict__ boff, int nb) {
    __shared__ int wsum[8];
    int i = threadIdx.x;
    int v = (i < nb) ? bsum[i] : 0;
    int total;
    int excl = block_excl_scan(v, wsum, total);
    if (i <= nb) boff[i] = excl;
}

__global__ void scan_p3(const int* __restrict__ tmp, const int* __restrict__ boff,
                        int* __restrict__ rp, int* __restrict__ cursor, int n, int nb) {
    int i = blockIdx.x * 256 + threadIdx.x;
    if (i < n) {
        int v = tmp[i] + __ldg(boff + blockIdx.x);
        rp[i] = v;
        cursor[i] = v;
    }
    if (i == 0) rp[n] = __ldg(boff + nb);
}

// 4 edges per thread (nE is divisible by 4 for this dataset; scalar tail kept)
__global__ void scatter_edges4(const int* __restrict__ src, const int* __restrict__ dst,
                               const float* __restrict__ w, int* __restrict__ cursor,
                               int2* __restrict__ pe, int nE) {
    int i = blockIdx.x * blockDim.x + threadIdx.x;
    int e0 = i * 4;
    if (e0 + 4 <= nE) {
        int4 s = __ldg((const int4*)(src + e0));
        int4 d = __ldg((const int4*)(dst + e0));
        float4 ww = __ldg((const float4*)(w + e0));
        int p0 = atomicAdd(&cursor[d.x], 1);
        pe[p0] = make_int2(s.x, __float_as_int(ww.x));
        int p1 = atomicAdd(&cursor[d.y], 1);
        pe[p1] = make_int2(s.y, __float_as_int(ww.y));
        int p2 = atomicAdd(&cursor[d.z], 1);
        pe[p2] = make_int2(s.z, __float_as_int(ww.z));
        int p3 = atomicAdd(&cursor[d.w], 1);
        pe[p3] = make_int2(s.w, __float_as_int(ww.w));
    } else {
        for (int e = e0; e < nE; e++) {
            int dd = __ldg(dst + e);
            int pos = atomicAdd(&cursor[dd], 1);
            pe[pos] = make_int2(__ldg(src + e), __float_as_int(__ldg(w + e)));
        }
    }
}

// ===========================================================================
// GEMM3: C[M,40] = H[M,128] @ W2[128,40], fp16 output (logits)
// ===========================================================================
__global__ void sgemm40(const float* __restrict__ H, const float* __restrict__ W,
                        __half* __restrict__ C, int M) {
    __shared__ float Ht[32][132];
    __shared__ float Ws[128][40];

    const int t = threadIdx.x;
    const int row0 = blockIdx.x * 32;

#pragma unroll
    for (int l = 0; l < 4; l++) {
        int q = t + l * 256;
        int r = q >> 5;
        int c4 = q & 31;
        float4 v = make_float4(0.f, 0.f, 0.f, 0.f);
        if (row0 + r < M)
            v = *reinterpret_cast<const float4*>(H + (size_t)(row0 + r) * 128 + c4 * 4);
        *reinterpret_cast<float4*>(&Ht[r][c4 * 4]) = v;
    }
#pragma unroll
    for (int l = 0; l < 20; l++) {
        int q = t + l * 256;
        Ws[q / 40][q % 40] = W[q];
    }
    __syncthreads();

    const int r = t >> 3;
    const int cg = t & 7;
    float acc[5] = {0.f, 0.f, 0.f, 0.f, 0.f};
#pragma unroll 8
    for (int k = 0; k < 128; k++) {
        float h = Ht[r][k];
#pragma unroll
        for (int j = 0; j < 5; j++)
            acc[j] = fmaf(h, Ws[k][cg * 5 + j], acc[j]);
    }
    int grow = row0 + r;
    if (grow < M) {
#pragma unroll
        for (int j = 0; j < 5; j++)
            C[(size_t)grow * 40 + cg * 5 + j] = __float2half_rn(acc[j]);
    }
}

// ===========================================================================
// Gather SpMM (feat=128, fp16 input, fp32 accumulate) + bias + ReLU, unroll 8
// ===========================================================================
__device__ __forceinline__ void acc4h(float& ax, float& ay, float& az, float& aw,
                                      float w, uint2 r) {
    float2 a01 = __half22float2(*reinterpret_cast<__half2*>(&r.x));
    float2 a23 = __half22float2(*reinterpret_cast<__half2*>(&r.y));
    ax = fmaf(w, a01.x, ax); ay = fmaf(w, a01.y, ay);
    az = fmaf(w, a23.x, az); aw = fmaf(w, a23.y, aw);
}

__global__ void __launch_bounds__(256) spmm_csr128h(
    const __half* __restrict__ H, const int* __restrict__ rp,
    const int2* __restrict__ pe, const float* __restrict__ bias,
    float* __restrict__ out, int M) {
    int row = blockIdx.x * 8 + (threadIdx.x >> 5);
    int lane = threadIdx.x & 31;
    if (row >= M) return;
    int p  = __ldg(rp + row);
    int pend = __ldg(rp + row + 1);

    const char* Hb = reinterpret_cast<const char*>(H) + lane * 8;  // 4 fp16 per lane
    float ax = 0.f, ay = 0.f, az = 0.f, aw = 0.f;

    for (; p + 8 <= pend; p += 8) {
        int2 e0 = __ldg(pe + p + 0), e1 = __ldg(pe + p + 1);
        int2 e2 = __ldg(pe + p + 2), e3 = __ldg(pe + p + 3);
        int2 e4 = __ldg(pe + p + 4), e5 = __ldg(pe + p + 5);
        int2 e6 = __ldg(pe + p + 6), e7 = __ldg(pe + p + 7);
        uint2 r0 = *reinterpret_cast<const uint2*>(Hb + (size_t)e0.x * 256);
        uint2 r1 = *reinterpret_cast<const uint2*>(Hb + (size_t)e1.x * 256);
        uint2 r2 = *reinterpret_cast<const uint2*>(Hb + (size_t)e2.x * 256);
        uint2 r3 = *reinterpret_cast<const uint2*>(Hb + (size_t)e3.x * 256);
        uint2 r4 = *reinterpret_cast<const uint2*>(Hb + (size_t)e4.x * 256);
        uint2 r5 = *reinterpret_cast<const uint2*>(Hb + (size_t)e5.x * 256);
        uint2 r6 = *reinterpret_cast<const uint2*>(Hb + (size_t)e6.x * 256);
        uint2 r7 = *reinterpret_cast<const uint2*>(Hb + (size_t)e7.x * 256);
        acc4h(ax, ay, az, aw, __int_as_float(e0.y), r0);
        acc4h(ax, ay, az, aw, __int_as_float(e1.y), r1);
        acc4h(ax, ay, az, aw, __int_as_float(e2.y), r2);
        acc4h(ax, ay, az, aw, __int_as_float(e3.y), r3);
        acc4h(ax, ay, az, aw, __int_as_float(e4.y), r4);
        acc4h(ax, ay, az, aw, __int_as_float(e5.y), r5);
        acc4h(ax, ay, az, aw, __int_as_float(e6.y), r6);
        acc4h(ax, ay, az, aw, __int_as_float(e7.y), r7);
    }
    for (; p + 2 <= pend; p += 2) {
        int2 e0 = __ldg(pe + p + 0), e1 = __ldg(pe + p + 1);
        uint2 r0 = *reinterpret_cast<const uint2*>(Hb + (size_t)e0.x * 256);
        uint2 r1 = *reinterpret_cast<const uint2*>(Hb + (size_t)e1.x * 256);
        acc4h(ax, ay, az, aw, __int_as_float(e0.y), r0);
        acc4h(ax, ay, az, aw, __int_as_float(e1.y), r1);
    }
    if (p < pend) {
        int2 e = __ldg(pe + p);
        uint2 r0 = *reinterpret_cast<const uint2*>(Hb + (size_t)e.x * 256);
        acc4h(ax, ay, az, aw, __int_as_float(e.y), r0);
    }

    float4 b4 = *reinterpret_cast<const float4*>(bias + lane * 4);
    float4 r4v;
    r4v.x = fmaxf(ax + b4.x, 0.f);
    r4v.y = fmaxf(ay + b4.y, 0.f);
    r4v.z = fmaxf(az + b4.z, 0.f);
    r4v.w = fmaxf(aw + b4.w, 0.f);
    *reinterpret_cast<float4*>(out + (size_t)row * 128 + lane * 4) = r4v;
}

// ===========================================================================
// Gather SpMM (feat=40, fp16 logits, fp32 accumulate) + bias + log_softmax
// ===========================================================================
__global__ void __launch_bounds__(256) spmm_csr40_lsm(
    const __half* __restrict__ C, const int* __restrict__ rp,
    const int2* __restrict__ pe, const float* __restrict__ b,
    float* __restrict__ out, int M) {
    int row = blockIdx.x * 8 + (threadIdx.x >> 5);
    int lane = threadIdx.x & 31;
    if (row >= M) return;
    int p  = __ldg(rp + row);
    int pend = __ldg(rp + row + 1);

    float a0 = 0.f, a1 = 0.f;
    for (; p + 2 <= pend; p += 2) {
        int2 e0 = __ldg(pe + p), e1 = __ldg(pe + p + 1);
        float w0 = __int_as_float(e0.y), w1 = __int_as_float(e1.y);
        const __half* c0 = C + (size_t)e0.x * 40;
        const __half* c1 = C + (size_t)e1.x * 40;
        float x0 = __half2float(__ldg(c0 + lane));
        float x1 = __half2float(__ldg(c1 + lane));
        float y0 = (lane < 8) ? __half2float(__ldg(c0 + 32 + lane)) : 0.f;
        float y1 = (lane < 8) ? __half2float(__ldg(c1 + 32 + lane)) : 0.f;
        a0 = fmaf(w0, x0, a0); a0 = fmaf(w1, x1, a0);
        a1 = fmaf(w0, y0, a1); a1 = fmaf(w1, y1, a1);
    }
    if (p < pend) {
        int2 e = __ldg(pe + p);
        float w = __int_as_float(e.y);
        const __half* c0 = C + (size_t)e.x * 40;
        a0 = fmaf(w, __half2float(__ldg(c0 + lane)), a0);
        if (lane < 8) a1 = fmaf(w, __half2float(__ldg(c0 + 32 + lane)), a1);
    }

    float v0 = a0 + __ldg(b + lane);
    float v1 = (lane < 8) ? (a1 + __ldg(b + 32 + lane)) : -INFINITY;

    float m = fmaxf(v0, v1);
#pragma unroll
    for (int o = 16; o > 0; o >>= 1) m = fmaxf(m, __shfl_xor_sync(0xffffffffu, m, o));
    float s = __expf(v0 - m) + ((lane < 8) ? __expf(v1 - m) : 0.f);
#pragma unroll
    for (int o = 16; o > 0; o >>= 1) s += __shfl_xor_sync(0xffffffffu, s, o);
    float ls = m + __logf(s);

    out[(size_t)row * 40 + lane] = v0 - ls;
    if (lane < 8) out[(size_t)row * 40 + 32 + lane] = v1 - ls;
}

// ===========================================================================
extern "C" void kernel_launch(void* const* d_in, const int* in_sizes, int n_in,
                              void* d_out, int out_size) {
    const float* x    = (const float*)d_in[0];
    const int*   esrc = (const int*)  d_in[1];
    const int*   edst = (const int*)  d_in[2];
    const float* ew   = (const float*)d_in[3];
    const float* W1   = (const float*)d_in[4];
    const float* b1   = (const float*)d_in[5];
    const float* Wh   = (const float*)d_in[6];
    const float* bh   = (const float*)d_in[7];
    const float* W2   = (const float*)d_in[8];
    const float* b2   = (const float*)d_in[9];
    float* out = (float*)d_out;

    const int M  = in_sizes[0] / NFEAT;   // 50000
    const int nE = in_sizes[1];           // 1600000

    __half *Ah, *Ch;
    float *B;
    int *cnt, *cursor, *rp, *tmp, *bsum, *boff;
    int2 *pe;
    cudaGetSymbolAddress((void**)&Ah, g_Ah);
    cudaGetSymbolAddress((void**)&B, g_B);
    cudaGetSymbolAddress((void**)&Ch, g_Ch);
    cudaGetSymbolAddress((void**)&cnt, g_cnt);
    cudaGetSymbolAddress((void**)&cursor, g_cursor);
    cudaGetSymbolAddress((void**)&rp, g_rp);
    cudaGetSymbolAddress((void**)&tmp, g_tmp);
    cudaGetSymbolAddress((void**)&bsum, g_bsum);
    cudaGetSymbolAddress((void**)&boff, g_boff);
    cudaGetSymbolAddress((void**)&pe, g_pe);

    static cudaStream_t s2 = nullptr;
    static cudaEvent_t evF = nullptr, evJ = nullptr;
    if (!s2) {
        cudaStreamCreateWithFlags(&s2, cudaStreamNonBlocking);
        cudaEventCreateWithFlags(&evF, cudaEventDisableTiming);
        cudaEventCreateWithFlags(&evJ, cudaEventDisableTiming);
        cudaFuncSetAttribute(mma_gemm128, cudaFuncAttributeMaxDynamicSharedMemorySize,
                             SM_U32 * 4);
    }

    const int nb = (M + 255) / 256;           // 196
    const int gemmBlocks = (M + 127) / 128;   // 391
    const int spmmBlocks = (M + 7) / 8;
    const int nE4 = (nE + 3) / 4;

    // ---- Fork: CSR build on s2, layer-1 GEMM on main stream ----
    cudaEventRecord(evF, 0);
    cudaStreamWaitEvent(s2, evF, 0);

    zero_int4<<<(M / 4 + 255) / 256, 256, 0, s2>>>((int4*)cnt, (M + 3) / 4);
    hist_dst4<<<((nE / 4) + 255) / 256, 256, 0, s2>>>((const int4*)edst, cnt, nE / 4);
    scan_p1<<<nb, 256, 0, s2>>>(cnt, tmp, bsum, M);
    scan_p2<<<1, 256, 0, s2>>>(bsum, boff, nb);
    scan_p3<<<nb, 256, 0, s2>>>(tmp, boff, rp, cursor, M, nb);
    scatter_edges4<<<(nE4 + 255) / 256, 256, 0, s2>>>(esrc, edst, ew, cursor, pe, nE);
    cudaEventRecord(evJ, s2);

    mma_gemm128<<<gemmBlocks, 256, SM_U32 * 4>>>(x, W1, Ah, M, NFEAT);

    cudaStreamWaitEvent(0, evJ, 0);   // join

    // Layer 1 aggregation
    spmm_csr128h<<<spmmBlocks, 256>>>(Ah, rp, pe, b1, B, M);

    // Layer 2
    mma_gemm128<<<gemmBlocks, 256, SM_U32 * 4>>>(B, Wh, Ah, M, NHID);
    spmm_csr128h<<<spmmBlocks, 256>>>(Ah, rp, pe, bh, B, M);

    // Layer 3 + log_softmax
    sgemm40<<<(M + 31) / 32, 256>>>(B, W2, Ch, M);
    spmm_csr40_lsm<<<spmmBlocks, 256>>>(Ch, rp, pe, b2, out, M);
}

// round 8
// speedup vs baseline: 6.4350x; 1.0118x over previous
#include <cuda_runtime.h>
#include <cuda_bf16.h>
#include <cuda_fp16.h>
#include <math.h>
#include <cstdint>

// ---------------------------------------------------------------------------
// GCN: 3x { H = A_sparse @ (H @ W) + b (,ReLU) } -> log_softmax
// N=50000, E=1.6M, 512 -> 128 -> 128 -> 40
// Round 8: fp16 hidden-state path end-to-end (spmm stores fp16, GEMMs take
//          fp16 input), 2-kernel scan, fewer launches. bf16 hi/lo HMMA GEMM,
//          fp32 accumulation everywhere.
// ---------------------------------------------------------------------------

#define NNODES 50000
#define NEDGES 1600000
#define NFEAT 512
#define NHID  128
#define NCLASS 40

// Scratch (__device__ globals; no allocations allowed)
__device__ __half g_Ah[NNODES * NHID];   // GEMM output / spmm input
__device__ __half g_Bh[NNODES * NHID];   // spmm output / GEMM input
__device__ __half g_Ch[NNODES * NCLASS]; // GEMM3 output (fp16 logits)
__device__ int    g_cnt[NNODES];
__device__ int    g_cursor[NNODES];
__device__ int    g_rp[NNODES + 1];
__device__ int    g_tmp[NNODES];
__device__ int    g_bsum[256];           // per-block sums (nb=196 <= 256)
__device__ int2   g_pe[NEDGES];          // packed (src, weight-bits)

// ===========================================================================
// helpers
// ===========================================================================
__device__ __forceinline__ void cvt_hilo(float x, float y, uint32_t& hi, uint32_t& lo) {
    __nv_bfloat16 hx = __float2bfloat16(x);
    __nv_bfloat16 hy = __float2bfloat16(y);
    float rx = x - __bfloat162float(hx);
    float ry = y - __bfloat162float(hy);
    __nv_bfloat162 H; H.x = hx; H.y = hy;
    __nv_bfloat162 L; L.x = __float2bfloat16(rx); L.y = __float2bfloat16(ry);
    hi = *reinterpret_cast<uint32_t*>(&H);
    lo = *reinterpret_cast<uint32_t*>(&L);
}

__device__ __forceinline__ void mma16816(float* d, const uint32_t* a, uint32_t b0, uint32_t b1) {
    asm volatile(
        "mma.sync.aligned.m16n8k16.row.col.f32.bf16.bf16.f32 "
        "{%0,%1,%2,%3}, {%4,%5,%6,%7}, {%8,%9}, {%0,%1,%2,%3};"
        : "+f"(d[0]), "+f"(d[1]), "+f"(d[2]), "+f"(d[3])
        : "r"(a[0]), "r"(a[1]), "r"(a[2]), "r"(a[3]), "r"(b0), "r"(b1));
}

// Load 4 consecutive elements as float4, for fp32 or fp16 source.
__device__ __forceinline__ float4 load4f(const float* p) {
    return *reinterpret_cast<const float4*>(p);
}
__device__ __forceinline__ float4 load4f(const __half* p) {
    uint2 u = *reinterpret_cast<const uint2*>(p);
    float2 a = __half22float2(*reinterpret_cast<__half2*>(&u.x));
    float2 b = __half22float2(*reinterpret_cast<__half2*>(&u.y));
    return make_float4(a.x, a.y, b.x, b.y);
}

// SMEM layout (u32 units). A tiles: [m=128][k2=32 + pad4]. B: [k2=32][n=128+8].
#define AH_OFF 0
#define AL_OFF 4608
#define BH_OFF 9216
#define BL_OFF 13568
#define SM_U32 17920   // 71680 bytes

// ===========================================================================
// mma.sync GEMM: C[M,128] = A[M,K] @ W[K,128]; A fp32 or fp16; fp16 out.
// bf16 hi/lo split, fp32 accumulate. CTA 128x128, 8 warps, K chunks of 64.
// ===========================================================================
template <typename TIn>
__global__ void __launch_bounds__(256) mma_gemm128(
    const TIn* __restrict__ A, const float* __restrict__ W,
    __half* __restrict__ C, int M, int K) {
    extern __shared__ uint32_t sm[];
    uint32_t* AH = sm + AH_OFF;
    uint32_t* AL = sm + AL_OFF;
    uint32_t* BH = sm + BH_OFF;
    uint32_t* BL = sm + BL_OFF;

    const int t = threadIdx.x;
    const int lane = t & 31;
    const int wid = t >> 5;
    const int warpM = wid >> 1;
    const int warpN = wid & 1;
    const int row0 = blockIdx.x * 128;

    float acc[2][8][4];
#pragma unroll
    for (int mt = 0; mt < 2; mt++)
#pragma unroll
        for (int nt = 0; nt < 8; nt++)
#pragma unroll
            for (int e = 0; e < 4; e++) acc[mt][nt][e] = 0.f;

    const int r4 = lane >> 2;
    const int q4 = lane & 3;

    const int nChunks = K >> 6;
    for (int c = 0; c < nChunks; c++) {
        const int k0 = c << 6;
        __syncthreads();

#pragma unroll
        for (int l = 0; l < 8; l++) {
            int q = t + l * 256;
            int m = q >> 4;
            int c4 = q & 15;
            float4 v = make_float4(0.f, 0.f, 0.f, 0.f);
            if (row0 + m < M)
                v = load4f(A + (size_t)(row0 + m) * K + k0 + c4 * 4);
            uint32_t h0, l0, h1, l1;
            cvt_hilo(v.x, v.y, h0, l0);
            cvt_hilo(v.z, v.w, h1, l1);
            int base = m * 36 + c4 * 2;
            AH[base] = h0; AH[base + 1] = h1;
            AL[base] = l0; AL[base + 1] = l1;
        }
#pragma unroll
        for (int l = 0; l < 16; l++) {
            int p = t + l * 256;
            int k2 = p >> 7;
            int n = p & 127;
            float v0 = __ldg(W + (size_t)(k0 + 2 * k2) * 128 + n);
            float v1 = __ldg(W + (size_t)(k0 + 2 * k2 + 1) * 128 + n);
            uint32_t h, lo;
            cvt_hilo(v0, v1, h, lo);
            BH[k2 * 136 + n] = h;
            BL[k2 * 136 + n] = lo;
        }
        __syncthreads();

#pragma unroll
        for (int k8 = 0; k8 < 4; k8++) {
            int klo = k8 * 8 + q4;
            uint32_t ah[2][4], al[2][4];
#pragma unroll
            for (int mt = 0; mt < 2; mt++) {
                int base = (warpM * 32 + mt * 16 + r4) * 36;
                ah[mt][0] = AH[base + klo];
                ah[mt][1] = AH[base + 8 * 36 + klo];
                ah[mt][2] = AH[base + klo + 4];
                ah[mt][3] = AH[base + 8 * 36 + klo + 4];
                al[mt][0] = AL[base + klo];
                al[mt][1] = AL[base + 8 * 36 + klo];
                al[mt][2] = AL[base + klo + 4];
                al[mt][3] = AL[base + 8 * 36 + klo + 4];
            }
#pragma unroll
            for (int nt = 0; nt < 8; nt++) {
                int nB = warpN * 64 + nt * 8 + r4;
                uint32_t bh0 = BH[klo * 136 + nB];
                uint32_t bh1 = BH[(klo + 4) * 136 + nB];
                uint32_t bl0 = BL[klo * 136 + nB];
                uint32_t bl1 = BL[(klo + 4) * 136 + nB];
#pragma unroll
                for (int mt = 0; mt < 2; mt++) {
                    mma16816(acc[mt][nt], ah[mt], bh0, bh1);
                    mma16816(acc[mt][nt], ah[mt], bl0, bl1);
                    mma16816(acc[mt][nt], al[mt], bh0, bh1);
                }
            }
        }
    }

#pragma unroll
    for (int mt = 0; mt < 2; mt++) {
        int rowA = row0 + warpM * 32 + mt * 16 + r4;
        int rowB = rowA + 8;
#pragma unroll
        for (int nt = 0; nt < 8; nt++) {
            int col = warpN * 64 + nt * 8 + q4 * 2;
            if (rowA < M)
                *reinterpret_cast<__half2*>(C + (size_t)rowA * 128 + col) =
                    __floats2half2_rn(acc[mt][nt][0], acc[mt][nt][1]);
            if (rowB < M)
                *reinterpret_cast<__half2*>(C + (size_t)rowB * 128 + col) =
                    __floats2half2_rn(acc[mt][nt][2], acc[mt][nt][3]);
        }
    }
}

// ===========================================================================
// CSR build: zero -> histogram -> 2-kernel scan -> scatter
// ===========================================================================
__global__ void zero_int4(int4* p, int n4) {
    int i = blockIdx.x * blockDim.x + threadIdx.x;
    if (i < n4) p[i] = make_int4(0, 0, 0, 0);
}

__global__ void hist_dst4(const int4* __restrict__ dst4, int* __restrict__ cnt, int n4) {
    int e = blockIdx.x * blockDim.x + threadIdx.x;
    if (e >= n4) return;
    int4 d = __ldg(dst4 + e);
    atomicAdd(&cnt[d.x], 1);
    atomicAdd(&cnt[d.y], 1);
    atomicAdd(&cnt[d.z], 1);
    atomicAdd(&cnt[d.w], 1);
}

__global__ void scan_p1(const int* __restrict__ cnt, int* __restrict__ tmp,
                        int* __restrict__ bsum, int n) {
    __shared__ int wsum[8];
    const int lane = threadIdx.x & 31;
    const int wid  = threadIdx.x >> 5;
    int i = blockIdx.x * 256 + threadIdx.x;
    int v = (i < n) ? cnt[i] : 0;
    int incl = v;
#pragma unroll
    for (int o = 1; o < 32; o <<= 1) {
        int tt = __shfl_up_sync(0xffffffffu, incl, o);
        if (lane >= o) incl += tt;
    }
    if (lane == 31) wsum[wid] = incl;
    __syncthreads();
    if (wid == 0) {
        int s = (lane < 8) ? wsum[lane] : 0;
#pragma unroll
        for (int o = 1; o < 8; o <<= 1) {
            int tt = __shfl_up_sync(0xffffffffu, s, o);
            if (lane >= o) s += tt;
        }
        if (lane < 8) wsum[lane] = s;
    }
    __syncthreads();
    int excl = (wid ? wsum[wid - 1] : 0) + incl - v;
    if (i < n) tmp[i] = excl;
    if (threadIdx.x == 255) bsum[blockIdx.x] = excl + v;   // block total
}

// Adds Sum(bsum[0..bid)) to each element; rp[n] = nE (known).
__global__ void scan_p3(const int* __restrict__ tmp, const int* __restrict__ bsum,
                        int* __restrict__ rp, int* __restrict__ cursor,
                        int n, int nb, int nE) {
    __shared__ int red[8];
    const int lane = threadIdx.x & 31;
    const int wid  = threadIdx.x >> 5;
    int v = (threadIdx.x < nb && threadIdx.x < blockIdx.x) ? __ldg(bsum + threadIdx.x) : 0;
#pragma unroll
    for (int o = 16; o > 0; o >>= 1) v += __shfl_xor_sync(0xffffffffu, v, o);
    if (lane == 0) red[wid] = v;
    __syncthreads();
    if (threadIdx.x == 0) {
        int s = 0;
#pragma unroll
        for (int j = 0; j < 8; j++) s += red[j];
        red[0] = s;
    }
    __syncthreads();
    int off = red[0];
    int i = blockIdx.x * 256 + threadIdx.x;
    if (i < n) {
        int val = tmp[i] + off;
        rp[i] = val;
        cursor[i] = val;
    }
    if (blockIdx.x == 0 && threadIdx.x == 0) rp[n] = nE;
}

__global__ void scatter_edges4(const int* __restrict__ src, const int* __restrict__ dst,
                               const float* __restrict__ w, int* __restrict__ cursor,
                               int2* __restrict__ pe, int nE) {
    int i = blockIdx.x * blockDim.x + threadIdx.x;
    int e0 = i * 4;
    if (e0 + 4 <= nE) {
        int4 s = __ldg((const int4*)(src + e0));
        int4 d = __ldg((const int4*)(dst + e0));
        float4 ww = __ldg((const float4*)(w + e0));
        int p0 = atomicAdd(&cursor[d.x], 1);
        pe[p0] = make_int2(s.x, __float_as_int(ww.x));
        int p1 = atomicAdd(&cursor[d.y], 1);
        pe[p1] = make_int2(s.y, __float_as_int(ww.y));
        int p2 = atomicAdd(&cursor[d.z], 1);
        pe[p2] = make_int2(s.z, __float_as_int(ww.z));
        int p3 = atomicAdd(&cursor[d.w], 1);
        pe[p3] = make_int2(s.w, __float_as_int(ww.w));
    } else {
        for (int e = e0; e < nE; e++) {
            int dd = __ldg(dst + e);
            int pos = atomicAdd(&cursor[dd], 1);
            pe[pos] = make_int2(__ldg(src + e), __float_as_int(__ldg(w + e)));
        }
    }
}

// ===========================================================================
// GEMM3: C[M,40] = H[M,128] @ W2[128,40]; fp16 in, fp16 out; fp32 math.
// ===========================================================================
__global__ void sgemm40(const __half* __restrict__ H, const float* __restrict__ W,
                        __half* __restrict__ C, int M) {
    __shared__ float Ht[32][132];
    __shared__ float Ws[128][40];

    const int t = threadIdx.x;
    const int row0 = blockIdx.x * 32;

    // Load H tile (32 x 128 fp16) = 4096 halves; 4 halves per slot, 1024 slots.
#pragma unroll
    for (int l = 0; l < 4; l++) {
        int q = t + l * 256;
        int r = q >> 5;
        int c4 = q & 31;
        float4 v = make_float4(0.f, 0.f, 0.f, 0.f);
        if (row0 + r < M)
            v = load4f(H + (size_t)(row0 + r) * 128 + c4 * 4);
        *reinterpret_cast<float4*>(&Ht[r][c4 * 4]) = v;
    }
#pragma unroll
    for (int l = 0; l < 20; l++) {
        int q = t + l * 256;
        Ws[q / 40][q % 40] = W[q];
    }
    __syncthreads();

    const int r = t >> 3;
    const int cg = t & 7;
    float acc[5] = {0.f, 0.f, 0.f, 0.f, 0.f};
#pragma unroll 8
    for (int k = 0; k < 128; k++) {
        float h = Ht[r][k];
#pragma unroll
        for (int j = 0; j < 5; j++)
            acc[j] = fmaf(h, Ws[k][cg * 5 + j], acc[j]);
    }
    int grow = row0 + r;
    if (grow < M) {
#pragma unroll
        for (int j = 0; j < 5; j++)
            C[(size_t)grow * 40 + cg * 5 + j] = __float2half_rn(acc[j]);
    }
}

// ===========================================================================
// Gather SpMM (feat=128, fp16 in, fp32 accum, fp16 out) + bias + ReLU
// ===========================================================================
__device__ __forceinline__ void acc4h(float& ax, float& ay, float& az, float& aw,
                                      float w, uint2 r) {
    float2 a01 = __half22float2(*reinterpret_cast<__half2*>(&r.x));
    float2 a23 = __half22float2(*reinterpret_cast<__half2*>(&r.y));
    ax = fmaf(w, a01.x, ax); ay = fmaf(w, a01.y, ay);
    az = fmaf(w, a23.x, az); aw = fmaf(w, a23.y, aw);
}

__global__ void __launch_bounds__(256) spmm_csr128h(
    const __half* __restrict__ H, const int* __restrict__ rp,
    const int2* __restrict__ pe, const float* __restrict__ bias,
    __half* __restrict__ out, int M) {
    int row = blockIdx.x * 8 + (threadIdx.x >> 5);
    int lane = threadIdx.x & 31;
    if (row >= M) return;
    int p  = __ldg(rp + row);
    int pend = __ldg(rp + row + 1);

    const char* Hb = reinterpret_cast<const char*>(H) + lane * 8;  // 4 fp16 per lane
    float ax = 0.f, ay = 0.f, az = 0.f, aw = 0.f;

    for (; p + 4 <= pend; p += 4) {
        int2 e0 = __ldg(pe + p + 0), e1 = __ldg(pe + p + 1);
        int2 e2 = __ldg(pe + p + 2), e3 = __ldg(pe + p + 3);
        uint2 r0 = *reinterpret_cast<const uint2*>(Hb + (size_t)e0.x * 256);
        uint2 r1 = *reinterpret_cast<const uint2*>(Hb + (size_t)e1.x * 256);
        uint2 r2 = *reinterpret_cast<const uint2*>(Hb + (size_t)e2.x * 256);
        uint2 r3 = *reinterpret_cast<const uint2*>(Hb + (size_t)e3.x * 256);
        acc4h(ax, ay, az, aw, __int_as_float(e0.y), r0);
        acc4h(ax, ay, az, aw, __int_as_float(e1.y), r1);
        acc4h(ax, ay, az, aw, __int_as_float(e2.y), r2);
        acc4h(ax, ay, az, aw, __int_as_float(e3.y), r3);
    }
    for (; p < pend; p++) {
        int2 e = __ldg(pe + p);
        uint2 r0 = *reinterpret_cast<const uint2*>(Hb + (size_t)e.x * 256);
        acc4h(ax, ay, az, aw, __int_as_float(e.y), r0);
    }

    float4 b4 = *reinterpret_cast<const float4*>(bias + lane * 4);
    __half2 o01 = __floats2half2_rn(fmaxf(ax + b4.x, 0.f), fmaxf(ay + b4.y, 0.f));
    __half2 o23 = __floats2half2_rn(fmaxf(az + b4.z, 0.f), fmaxf(aw + b4.w, 0.f));
    uint2 st;
    st.x = *reinterpret_cast<uint32_t*>(&o01);
    st.y = *reinterpret_cast<uint32_t*>(&o23);
    *reinterpret_cast<uint2*>(reinterpret_cast<char*>(out) + (size_t)row * 256 + lane * 8) = st;
}

// ===========================================================================
// Gather SpMM (feat=40, fp16 logits, fp32 accum) + bias + log_softmax
// ===========================================================================
__global__ void __launch_bounds__(256) spmm_csr40_lsm(
    const __half* __restrict__ C, const int* __restrict__ rp,
    const int2* __restrict__ pe, const float* __restrict__ b,
    float* __restrict__ out, int M) {
    int row = blockIdx.x * 8 + (threadIdx.x >> 5);
    int lane = threadIdx.x & 31;
    if (row >= M) return;
    int p  = __ldg(rp + row);
    int pend = __ldg(rp + row + 1);

    float a0 = 0.f, a1 = 0.f;
    for (; p + 2 <= pend; p += 2) {
        int2 e0 = __ldg(pe + p), e1 = __ldg(pe + p + 1);
        float w0 = __int_as_float(e0.y), w1 = __int_as_float(e1.y);
        const __half* c0 = C + (size_t)e0.x * 40;
        const __half* c1 = C + (size_t)e1.x * 40;
        float x0 = __half2float(__ldg(c0 + lane));
        float x1 = __half2float(__ldg(c1 + lane));
        float y0 = (lane < 8) ? __half2float(__ldg(c0 + 32 + lane)) : 0.f;
        float y1 = (lane < 8) ? __half2float(__ldg(c1 + 32 + lane)) : 0.f;
        a0 = fmaf(w0, x0, a0); a0 = fmaf(w1, x1, a0);
        a1 = fmaf(w0, y0, a1); a1 = fmaf(w1, y1, a1);
    }
    if (p < pend) {
        int2 e = __ldg(pe + p);
        float w = __int_as_float(e.y);
        const __half* c0 = C + (size_t)e.x * 40;
        a0 = fmaf(w, __half2float(__ldg(c0 + lane)), a0);
        if (lane < 8) a1 = fmaf(w, __half2float(__ldg(c0 + 32 + lane)), a1);
    }

    float v0 = a0 + __ldg(b + lane);
    float v1 = (lane < 8) ? (a1 + __ldg(b + 32 + lane)) : -INFINITY;

    float m = fmaxf(v0, v1);
#pragma unroll
    for (int o = 16; o > 0; o >>= 1) m = fmaxf(m, __shfl_xor_sync(0xffffffffu, m, o));
    float s = __expf(v0 - m) + ((lane < 8) ? __expf(v1 - m) : 0.f);
#pragma unroll
    for (int o = 16; o > 0; o >>= 1) s += __shfl_xor_sync(0xffffffffu, s, o);
    float ls = m + __logf(s);

    out[(size_t)row * 40 + lane] = v0 - ls;
    if (lane < 8) out[(size_t)row * 40 + 32 + lane] = v1 - ls;
}

// ===========================================================================
extern "C" void kernel_launch(void* const* d_in, const int* in_sizes, int n_in,
                              void* d_out, int out_size) {
    const float* x    = (const float*)d_in[0];
    const int*   esrc = (const int*)  d_in[1];
    const int*   edst = (const int*)  d_in[2];
    const float* ew   = (const float*)d_in[3];
    const float* W1   = (const float*)d_in[4];
    const float* b1   = (const float*)d_in[5];
    const float* Wh   = (const float*)d_in[6];
    const float* bh   = (const float*)d_in[7];
    const float* W2   = (const float*)d_in[8];
    const float* b2   = (const float*)d_in[9];
    float* out = (float*)d_out;

    const int M  = in_sizes[0] / NFEAT;   // 50000
    const int nE = in_sizes[1];           // 1600000

    __half *Ah, *Bh, *Ch;
    int *cnt, *cursor, *rp, *tmp, *bsum;
    int2 *pe;
    cudaGetSymbolAddress((void**)&Ah, g_Ah);
    cudaGetSymbolAddress((void**)&Bh, g_Bh);
    cudaGetSymbolAddress((void**)&Ch, g_Ch);
    cudaGetSymbolAddress((void**)&cnt, g_cnt);
    cudaGetSymbolAddress((void**)&cursor, g_cursor);
    cudaGetSymbolAddress((void**)&rp, g_rp);
    cudaGetSymbolAddress((void**)&tmp, g_tmp);
    cudaGetSymbolAddress((void**)&bsum, g_bsum);
    cudaGetSymbolAddress((void**)&pe, g_pe);

    static cudaStream_t s2 = nullptr;
    static cudaEvent_t evF = nullptr, evJ = nullptr;
    if (!s2) {
        cudaStreamCreateWithFlags(&s2, cudaStreamNonBlocking);
        cudaEventCreateWithFlags(&evF, cudaEventDisableTiming);
        cudaEventCreateWithFlags(&evJ, cudaEventDisableTiming);
        cudaFuncSetAttribute(mma_gemm128<float>,
                             cudaFuncAttributeMaxDynamicSharedMemorySize, SM_U32 * 4);
        cudaFuncSetAttribute(mma_gemm128<__half>,
                             cudaFuncAttributeMaxDynamicSharedMemorySize, SM_U32 * 4);
    }

    const int nb = (M + 255) / 256;           // 196
    const int gemmBlocks = (M + 127) / 128;   // 391
    const int spmmBlocks = (M + 7) / 8;
    const int nE4 = (nE + 3) / 4;

    // ---- Fork: CSR build on s2, layer-1 GEMM on main stream ----
    cudaEventRecord(evF, 0);
    cudaStreamWaitEvent(s2, evF, 0);

    zero_int4<<<(M / 4 + 255) / 256, 256, 0, s2>>>((int4*)cnt, (M + 3) / 4);
    hist_dst4<<<((nE / 4) + 255) / 256, 256, 0, s2>>>((const int4*)edst, cnt, nE / 4);
    scan_p1<<<nb, 256, 0, s2>>>(cnt, tmp, bsum, M);
    scan_p3<<<nb, 256, 0, s2>>>(tmp, bsum, rp, cursor, M, nb, nE);
    scatter_edges4<<<(nE4 + 255) / 256, 256, 0, s2>>>(esrc, edst, ew, cursor, pe, nE);
    cudaEventRecord(evJ, s2);

    mma_gemm128<float><<<gemmBlocks, 256, SM_U32 * 4>>>(x, W1, Ah, M, NFEAT);

    cudaStreamWaitEvent(0, evJ, 0);   // join

    // Layer 1 aggregation (fp16 out)
    spmm_csr128h<<<spmmBlocks, 256>>>(Ah, rp, pe, b1, Bh, M);

    // Layer 2 (fp16 in)
    mma_gemm128<__half><<<gemmBlocks, 256, SM_U32 * 4>>>(Bh, Wh, Ah, M, NHID);
    spmm_csr128h<<<spmmBlocks, 256>>>(Ah, rp, pe, bh, Bh, M);

    // Layer 3 + log_softmax
    sgemm40<<<(M + 31) / 32, 256>>>(Bh, W2, Ch, M);
    spmm_csr40_lsm<<<spmmBlocks, 256>>>(Ch, rp, pe, b2, out, M);
}

// round 9
// speedup vs baseline: 7.0511x; 1.0957x over previous
#include <cuda_runtime.h>
#include <cuda_bf16.h>
#include <cuda_fp16.h>
#include <math.h>
#include <cstdint>

// ---------------------------------------------------------------------------
// GCN: 3x { H = A_sparse @ (H @ W) + b (,ReLU) } -> log_softmax
// N=50000, E=1.6M, 512 -> 128 -> 128 -> 40
// Round 9: pre-packed bf16 hi/lo weights (GEMM B-stage = pure copies),
//          2 CTA/SM GEMM occupancy. fp16 hidden path, CSR fork, 2-kernel scan.
// ---------------------------------------------------------------------------

#define NNODES 50000
#define NEDGES 1600000
#define NFEAT 512
#define NHID  128
#define NCLASS 40

// Scratch (__device__ globals; no allocations allowed)
__device__ __half g_Ah[NNODES * NHID];   // GEMM output / spmm input
__device__ __half g_Bh[NNODES * NHID];   // spmm output / GEMM input
__device__ __half g_Ch[NNODES * NCLASS]; // GEMM3 output (fp16 logits)
__device__ int    g_cnt[NNODES];
__device__ int    g_cursor[NNODES];
__device__ int    g_rp[NNODES + 1];
__device__ int    g_tmp[NNODES];
__device__ int    g_bsum[256];
__device__ int2   g_pe[NEDGES];          // packed (src, weight-bits)
// Pre-packed weights: bf16x2 k-pairs, layout [k2][n] (n=128)
__device__ uint32_t g_W1h[256 * 128];
__device__ uint32_t g_W1l[256 * 128];
__device__ uint32_t g_Whh[64 * 128];
__device__ uint32_t g_Whl[64 * 128];

// ===========================================================================
// helpers
// ===========================================================================
__device__ __forceinline__ void cvt_hilo(float x, float y, uint32_t& hi, uint32_t& lo) {
    __nv_bfloat16 hx = __float2bfloat16(x);
    __nv_bfloat16 hy = __float2bfloat16(y);
    float rx = x - __bfloat162float(hx);
    float ry = y - __bfloat162float(hy);
    __nv_bfloat162 H; H.x = hx; H.y = hy;
    __nv_bfloat162 L; L.x = __float2bfloat16(rx); L.y = __float2bfloat16(ry);
    hi = *reinterpret_cast<uint32_t*>(&H);
    lo = *reinterpret_cast<uint32_t*>(&L);
}

__device__ __forceinline__ void mma16816(float* d, const uint32_t* a, uint32_t b0, uint32_t b1) {
    asm volatile(
        "mma.sync.aligned.m16n8k16.row.col.f32.bf16.bf16.f32 "
        "{%0,%1,%2,%3}, {%4,%5,%6,%7}, {%8,%9}, {%0,%1,%2,%3};"
        : "+f"(d[0]), "+f"(d[1]), "+f"(d[2]), "+f"(d[3])
        : "r"(a[0]), "r"(a[1]), "r"(a[2]), "r"(a[3]), "r"(b0), "r"(b1));
}

__device__ __forceinline__ float4 load4f(const float* p) {
    return *reinterpret_cast<const float4*>(p);
}
__device__ __forceinline__ float4 load4f(const __half* p) {
    uint2 u = *reinterpret_cast<const uint2*>(p);
    float2 a = __half22float2(*reinterpret_cast<__half2*>(&u.x));
    float2 b = __half22float2(*reinterpret_cast<__half2*>(&u.y));
    return make_float4(a.x, a.y, b.x, b.y);
}

// SMEM layout (u32 units). A tiles: [m=128][k2=32 + pad4]. B: [k2=32][n=128+8].
#define AH_OFF 0
#define AL_OFF 4608
#define BH_OFF 9216
#define BL_OFF 13568
#define SM_U32 17920   // 71680 bytes

// ===========================================================================
// Weight pre-pack: W[K][128] fp32 -> hi/lo bf16x2 planes [K/2][128]
// ===========================================================================
__global__ void conv_weights(const float* __restrict__ W1, const float* __restrict__ Wh,
                             uint32_t* __restrict__ W1h, uint32_t* __restrict__ W1l,
                             uint32_t* __restrict__ Whh, uint32_t* __restrict__ Whl) {
    int i = blockIdx.x * 256 + threadIdx.x;
    if (i < 256 * 128) {
        int k2 = i >> 7, n = i & 127;
        float v0 = __ldg(W1 + (size_t)(2 * k2) * 128 + n);
        float v1 = __ldg(W1 + (size_t)(2 * k2 + 1) * 128 + n);
        uint32_t h, lo;
        cvt_hilo(v0, v1, h, lo);
        W1h[i] = h; W1l[i] = lo;
    } else if (i < 256 * 128 + 64 * 128) {
        int j = i - 256 * 128;
        int k2 = j >> 7, n = j & 127;
        float v0 = __ldg(Wh + (size_t)(2 * k2) * 128 + n);
        float v1 = __ldg(Wh + (size_t)(2 * k2 + 1) * 128 + n);
        uint32_t h, lo;
        cvt_hilo(v0, v1, h, lo);
        Whh[j] = h; Whl[j] = lo;
    }
}

// ===========================================================================
// mma.sync GEMM: C[M,128] = A[M,K] @ W[K,128]; A fp32/fp16; W pre-packed.
// bf16 hi/lo split, fp32 accumulate, fp16 out. CTA 128x128, 8 warps.
// ===========================================================================
template <typename TIn>
__global__ void __launch_bounds__(256, 2) mma_gemm128(
    const TIn* __restrict__ A,
    const uint32_t* __restrict__ Wph, const uint32_t* __restrict__ Wpl,
    __half* __restrict__ C, int M, int K) {
    extern __shared__ uint32_t sm[];
    uint32_t* AH = sm + AH_OFF;
    uint32_t* AL = sm + AL_OFF;
    uint32_t* BH = sm + BH_OFF;
    uint32_t* BL = sm + BL_OFF;

    const int t = threadIdx.x;
    const int lane = t & 31;
    const int wid = t >> 5;
    const int warpM = wid >> 1;
    const int warpN = wid & 1;
    const int row0 = blockIdx.x * 128;

    float acc[2][8][4];
#pragma unroll
    for (int mt = 0; mt < 2; mt++)
#pragma unroll
        for (int nt = 0; nt < 8; nt++)
#pragma unroll
            for (int e = 0; e < 4; e++) acc[mt][nt][e] = 0.f;

    const int r4 = lane >> 2;
    const int q4 = lane & 3;

    const int nChunks = K >> 6;
    for (int c = 0; c < nChunks; c++) {
        const int k0 = c << 6;
        const int k0h = c << 5;          // k2 base
        __syncthreads();

        // ---- stage A chunk: 128 rows x 64 k -> hi/lo bf16x2 ----
#pragma unroll
        for (int l = 0; l < 8; l++) {
            int q = t + l * 256;
            int m = q >> 4;
            int c4 = q & 15;
            float4 v = make_float4(0.f, 0.f, 0.f, 0.f);
            if (row0 + m < M)
                v = load4f(A + (size_t)(row0 + m) * K + k0 + c4 * 4);
            uint32_t h0, l0, h1, l1;
            cvt_hilo(v.x, v.y, h0, l0);
            cvt_hilo(v.z, v.w, h1, l1);
            int base = m * 36 + c4 * 2;
            AH[base] = h0; AH[base + 1] = h1;
            AL[base] = l0; AL[base + 1] = l1;
        }
        // ---- stage W chunk: pure uint4 copies from pre-packed planes ----
#pragma unroll
        for (int l = 0; l < 4; l++) {
            int q = t + l * 256;         // 0..1023 uint4 slots
            int k2 = q >> 5;             // 0..31
            int n4 = q & 31;             // 0..31
            size_t goff = (size_t)(k0h + k2) * 128 + n4 * 4;
            uint4 vh = __ldg(reinterpret_cast<const uint4*>(Wph + goff));
            uint4 vl = __ldg(reinterpret_cast<const uint4*>(Wpl + goff));
            *reinterpret_cast<uint4*>(&BH[k2 * 136 + n4 * 4]) = vh;
            *reinterpret_cast<uint4*>(&BL[k2 * 136 + n4 * 4]) = vl;
        }
        __syncthreads();

#pragma unroll
        for (int k8 = 0; k8 < 4; k8++) {
            int klo = k8 * 8 + q4;
            uint32_t ah[2][4], al[2][4];
#pragma unroll
            for (int mt = 0; mt < 2; mt++) {
                int base = (warpM * 32 + mt * 16 + r4) * 36;
                ah[mt][0] = AH[base + klo];
                ah[mt][1] = AH[base + 8 * 36 + klo];
                ah[mt][2] = AH[base + klo + 4];
                ah[mt][3] = AH[base + 8 * 36 + klo + 4];
                al[mt][0] = AL[base + klo];
                al[mt][1] = AL[base + 8 * 36 + klo];
                al[mt][2] = AL[base + klo + 4];
                al[mt][3] = AL[base + 8 * 36 + klo + 4];
            }
#pragma unroll
            for (int nt = 0; nt < 8; nt++) {
                int nB = warpN * 64 + nt * 8 + r4;
                uint32_t bh0 = BH[klo * 136 + nB];
                uint32_t bh1 = BH[(klo + 4) * 136 + nB];
                uint32_t bl0 = BL[klo * 136 + nB];
                uint32_t bl1 = BL[(klo + 4) * 136 + nB];
#pragma unroll
                for (int mt = 0; mt < 2; mt++) {
                    mma16816(acc[mt][nt], ah[mt], bh0, bh1);
                    mma16816(acc[mt][nt], ah[mt], bl0, bl1);
                    mma16816(acc[mt][nt], al[mt], bh0, bh1);
                }
            }
        }
    }

#pragma unroll
    for (int mt = 0; mt < 2; mt++) {
        int rowA = row0 + warpM * 32 + mt * 16 + r4;
        int rowB = rowA + 8;
#pragma unroll
        for (int nt = 0; nt < 8; nt++) {
            int col = warpN * 64 + nt * 8 + q4 * 2;
            if (rowA < M)
                *reinterpret_cast<__half2*>(C + (size_t)rowA * 128 + col) =
                    __floats2half2_rn(acc[mt][nt][0], acc[mt][nt][1]);
            if (rowB < M)
                *reinterpret_cast<__half2*>(C + (size_t)rowB * 128 + col) =
                    __floats2half2_rn(acc[mt][nt][2], acc[mt][nt][3]);
        }
    }
}

// ===========================================================================
// CSR build: zero -> histogram -> 2-kernel scan -> scatter
// ===========================================================================
__global__ void zero_int4(int4* p, int n4) {
    int i = blockIdx.x * blockDim.x + threadIdx.x;
    if (i < n4) p[i] = make_int4(0, 0, 0, 0);
}

__global__ void hist_dst4(const int4* __restrict__ dst4, int* __restrict__ cnt, int n4) {
    int e = blockIdx.x * blockDim.x + threadIdx.x;
    if (e >= n4) return;
    int4 d = __ldg(dst4 + e);
    atomicAdd(&cnt[d.x], 1);
    atomicAdd(&cnt[d.y], 1);
    atomicAdd(&cnt[d.z], 1);
    atomicAdd(&cnt[d.w], 1);
}

__global__ void scan_p1(const int* __restrict__ cnt, int* __restrict__ tmp,
                        int* __restrict__ bsum, int n) {
    __shared__ int wsum[8];
    const int lane = threadIdx.x & 31;
    const int wid  = threadIdx.x >> 5;
    int i = blockIdx.x * 256 + threadIdx.x;
    int v = (i < n) ? cnt[i] : 0;
    int incl = v;
#pragma unroll
    for (int o = 1; o < 32; o <<= 1) {
        int tt = __shfl_up_sync(0xffffffffu, incl, o);
        if (lane >= o) incl += tt;
    }
    if (lane == 31) wsum[wid] = incl;
    __syncthreads();
    if (wid == 0) {
        int s = (lane < 8) ? wsum[lane] : 0;
#pragma unroll
        for (int o = 1; o < 8; o <<= 1) {
            int tt = __shfl_up_sync(0xffffffffu, s, o);
            if (lane >= o) s += tt;
        }
        if (lane < 8) wsum[lane] = s;
    }
    __syncthreads();
    int excl = (wid ? wsum[wid - 1] : 0) + incl - v;
    if (i < n) tmp[i] = excl;
    if (threadIdx.x == 255) bsum[blockIdx.x] = excl + v;
}

__global__ void scan_p3(const int* __restrict__ tmp, const int* __restrict__ bsum,
                        int* __restrict__ rp, int* __restrict__ cursor,
                        int n, int nb, int nE) {
    __shared__ int red[8];
    const int lane = threadIdx.x & 31;
    const int wid  = threadIdx.x >> 5;
    int v = (threadIdx.x < nb && threadIdx.x < blockIdx.x) ? __ldg(bsum + threadIdx.x) : 0;
#pragma unroll
    for (int o = 16; o > 0; o >>= 1) v += __shfl_xor_sync(0xffffffffu, v, o);
    if (lane == 0) red[wid] = v;
    __syncthreads();
    if (threadIdx.x == 0) {
        int s = 0;
#pragma unroll
        for (int j = 0; j < 8; j++) s += red[j];
        red[0] = s;
    }
    __syncthreads();
    int off = red[0];
    int i = blockIdx.x * 256 + threadIdx.x;
    if (i < n) {
        int val = tmp[i] + off;
        rp[i] = val;
        cursor[i] = val;
    }
    if (blockIdx.x == 0 && threadIdx.x == 0) rp[n] = nE;
}

__global__ void scatter_edges4(const int* __restrict__ src, const int* __restrict__ dst,
                               const float* __restrict__ w, int* __restrict__ cursor,
                               int2* __restrict__ pe, int nE) {
    int i = blockIdx.x * blockDim.x + threadIdx.x;
    int e0 = i * 4;
    if (e0 + 4 <= nE) {
        int4 s = __ldg((const int4*)(src + e0));
        int4 d = __ldg((const int4*)(dst + e0));
        float4 ww = __ldg((const float4*)(w + e0));
        int p0 = atomicAdd(&cursor[d.x], 1);
        pe[p0] = make_int2(s.x, __float_as_int(ww.x));
        int p1 = atomicAdd(&cursor[d.y], 1);
        pe[p1] = make_int2(s.y, __float_as_int(ww.y));
        int p2 = atomicAdd(&cursor[d.z], 1);
        pe[p2] = make_int2(s.z, __float_as_int(ww.z));
        int p3 = atomicAdd(&cursor[d.w], 1);
        pe[p3] = make_int2(s.w, __float_as_int(ww.w));
    } else {
        for (int e = e0; e < nE; e++) {
            int dd = __ldg(dst + e);
            int pos = atomicAdd(&cursor[dd], 1);
            pe[pos] = make_int2(__ldg(src + e), __float_as_int(__ldg(w + e)));
        }
    }
}

// ===========================================================================
// GEMM3: C[M,40] = H[M,128] @ W2[128,40]; fp16 in, fp16 out; fp32 math.
// ===========================================================================
__global__ void sgemm40(const __half* __restrict__ H, const float* __restrict__ W,
                        __half* __restrict__ C, int M) {
    __shared__ float Ht[32][132];
    __shared__ float Ws[128][40];

    const int t = threadIdx.x;
    const int row0 = blockIdx.x * 32;

#pragma unroll
    for (int l = 0; l < 4; l++) {
        int q = t + l * 256;
        int r = q >> 5;
        int c4 = q & 31;
        float4 v = make_float4(0.f, 0.f, 0.f, 0.f);
        if (row0 + r < M)
            v = load4f(H + (size_t)(row0 + r) * 128 + c4 * 4);
        *reinterpret_cast<float4*>(&Ht[r][c4 * 4]) = v;
    }
#pragma unroll
    for (int l = 0; l < 20; l++) {
        int q = t + l * 256;
        Ws[q / 40][q % 40] = W[q];
    }
    __syncthreads();

    const int r = t >> 3;
    const int cg = t & 7;
    float acc[5] = {0.f, 0.f, 0.f, 0.f, 0.f};
#pragma unroll 8
    for (int k = 0; k < 128; k++) {
        float h = Ht[r][k];
#pragma unroll
        for (int j = 0; j < 5; j++)
            acc[j] = fmaf(h, Ws[k][cg * 5 + j], acc[j]);
    }
    int grow = row0 + r;
    if (grow < M) {
#pragma unroll
        for (int j = 0; j < 5; j++)
            C[(size_t)grow * 40 + cg * 5 + j] = __float2half_rn(acc[j]);
    }
}

// ===========================================================================
// Gather SpMM (feat=128, fp16 in, fp32 accum, fp16 out) + bias + ReLU
// ===========================================================================
__device__ __forceinline__ void acc4h(float& ax, float& ay, float& az, float& aw,
                                      float w, uint2 r) {
    float2 a01 = __half22float2(*reinterpret_cast<__half2*>(&r.x));
    float2 a23 = __half22float2(*reinterpret_cast<__half2*>(&r.y));
    ax = fmaf(w, a01.x, ax); ay = fmaf(w, a01.y, ay);
    az = fmaf(w, a23.x, az); aw = fmaf(w, a23.y, aw);
}

__global__ void __launch_bounds__(256) spmm_csr128h(
    const __half* __restrict__ H, const int* __restrict__ rp,
    const int2* __restrict__ pe, const float* __restrict__ bias,
    __half* __restrict__ out, int M) {
    int row = blockIdx.x * 8 + (threadIdx.x >> 5);
    int lane = threadIdx.x & 31;
    if (row >= M) return;
    int p  = __ldg(rp + row);
    int pend = __ldg(rp + row + 1);

    const char* Hb = reinterpret_cast<const char*>(H) + lane * 8;
    float ax = 0.f, ay = 0.f, az = 0.f, aw = 0.f;

    for (; p + 4 <= pend; p += 4) {
        int2 e0 = __ldg(pe + p + 0), e1 = __ldg(pe + p + 1);
        int2 e2 = __ldg(pe + p + 2), e3 = __ldg(pe + p + 3);
        uint2 r0 = *reinterpret_cast<const uint2*>(Hb + (size_t)e0.x * 256);
        uint2 r1 = *reinterpret_cast<const uint2*>(Hb + (size_t)e1.x * 256);
        uint2 r2 = *reinterpret_cast<const uint2*>(Hb + (size_t)e2.x * 256);
        uint2 r3 = *reinterpret_cast<const uint2*>(Hb + (size_t)e3.x * 256);
        acc4h(ax, ay, az, aw, __int_as_float(e0.y), r0);
        acc4h(ax, ay, az, aw, __int_as_float(e1.y), r1);
        acc4h(ax, ay, az, aw, __int_as_float(e2.y), r2);
        acc4h(ax, ay, az, aw, __int_as_float(e3.y), r3);
    }
    for (; p < pend; p++) {
        int2 e = __ldg(pe + p);
        uint2 r0 = *reinterpret_cast<const uint2*>(Hb + (size_t)e.x * 256);
        acc4h(ax, ay, az, aw, __int_as_float(e.y), r0);
    }

    float4 b4 = *reinterpret_cast<const float4*>(bias + lane * 4);
    __half2 o01 = __floats2half2_rn(fmaxf(ax + b4.x, 0.f), fmaxf(ay + b4.y, 0.f));
    __half2 o23 = __floats2half2_rn(fmaxf(az + b4.z, 0.f), fmaxf(aw + b4.w, 0.f));
    uint2 st;
    st.x = *reinterpret_cast<uint32_t*>(&o01);
    st.y = *reinterpret_cast<uint32_t*>(&o23);
    *reinterpret_cast<uint2*>(reinterpret_cast<char*>(out) + (size_t)row * 256 + lane * 8) = st;
}

// ===========================================================================
// Gather SpMM (feat=40, fp16 logits, fp32 accum) + bias + log_softmax
// ===========================================================================
__global__ void __launch_bounds__(256) spmm_csr40_lsm(
    const __half* __restrict__ C, const int* __restrict__ rp,
    const int2* __restrict__ pe, const float* __restrict__ b,
    float* __restrict__ out, int M) {
    int row = blockIdx.x * 8 + (threadIdx.x >> 5);
    int lane = threadIdx.x & 31;
    if (row >= M) return;
    int p  = __ldg(rp + row);
    int pend = __ldg(rp + row + 1);

    float a0 = 0.f, a1 = 0.f;
    for (; p + 2 <= pend; p += 2) {
        int2 e0 = __ldg(pe + p), e1 = __ldg(pe + p + 1);
        float w0 = __int_as_float(e0.y), w1 = __int_as_float(e1.y);
        const __half* c0 = C + (size_t)e0.x * 40;
        const __half* c1 = C + (size_t)e1.x * 40;
        float x0 = __half2float(__ldg(c0 + lane));
        float x1 = __half2float(__ldg(c1 + lane));
        float y0 = (lane < 8) ? __half2float(__ldg(c0 + 32 + lane)) : 0.f;
        float y1 = (lane < 8) ? __half2float(__ldg(c1 + 32 + lane)) : 0.f;
        a0 = fmaf(w0, x0, a0); a0 = fmaf(w1, x1, a0);
        a1 = fmaf(w0, y0, a1); a1 = fmaf(w1, y1, a1);
    }
    if (p < pend) {
        int2 e = __ldg(pe + p);
        float w = __int_as_float(e.y);
        const __half* c0 = C + (size_t)e.x * 40;
        a0 = fmaf(w, __half2float(__ldg(c0 + lane)), a0);
        if (lane < 8) a1 = fmaf(w, __half2float(__ldg(c0 + 32 + lane)), a1);
    }

    float v0 = a0 + __ldg(b + lane);
    float v1 = (lane < 8) ? (a1 + __ldg(b + 32 + lane)) : -INFINITY;

    float m = fmaxf(v0, v1);
#pragma unroll
    for (int o = 16; o > 0; o >>= 1) m = fmaxf(m, __shfl_xor_sync(0xffffffffu, m, o));
    float s = __expf(v0 - m) + ((lane < 8) ? __expf(v1 - m) : 0.f);
#pragma unroll
    for (int o = 16; o > 0; o >>= 1) s += __shfl_xor_sync(0xffffffffu, s, o);
    float ls = m + __logf(s);

    out[(size_t)row * 40 + lane] = v0 - ls;
    if (lane < 8) out[(size_t)row * 40 + 32 + lane] = v1 - ls;
}

// ===========================================================================
extern "C" void kernel_launch(void* const* d_in, const int* in_sizes, int n_in,
                              void* d_out, int out_size) {
    const float* x    = (const float*)d_in[0];
    const int*   esrc = (const int*)  d_in[1];
    const int*   edst = (const int*)  d_in[2];
    const float* ew   = (const float*)d_in[3];
    const float* W1   = (const float*)d_in[4];
    const float* b1   = (const float*)d_in[5];
    const float* Wh   = (const float*)d_in[6];
    const float* bh   = (const float*)d_in[7];
    const float* W2   = (const float*)d_in[8];
    const float* b2   = (const float*)d_in[9];
    float* out = (float*)d_out;

    const int M  = in_sizes[0] / NFEAT;   // 50000
    const int nE = in_sizes[1];           // 1600000

    __half *Ah, *Bh, *Ch;
    int *cnt, *cursor, *rp, *tmp, *bsum;
    int2 *pe;
    uint32_t *W1h, *W1l, *Whh, *Whl;
    cudaGetSymbolAddress((void**)&Ah, g_Ah);
    cudaGetSymbolAddress((void**)&Bh, g_Bh);
    cudaGetSymbolAddress((void**)&Ch, g_Ch);
    cudaGetSymbolAddress((void**)&cnt, g_cnt);
    cudaGetSymbolAddress((void**)&cursor, g_cursor);
    cudaGetSymbolAddress((void**)&rp, g_rp);
    cudaGetSymbolAddress((void**)&tmp, g_tmp);
    cudaGetSymbolAddress((void**)&bsum, g_bsum);
    cudaGetSymbolAddress((void**)&pe, g_pe);
    cudaGetSymbolAddress((void**)&W1h, g_W1h);
    cudaGetSymbolAddress((void**)&W1l, g_W1l);
    cudaGetSymbolAddress((void**)&Whh, g_Whh);
    cudaGetSymbolAddress((void**)&Whl, g_Whl);

    static cudaStream_t s2 = nullptr;
    static cudaEvent_t evF = nullptr, evJ = nullptr;
    if (!s2) {
        cudaStreamCreateWithFlags(&s2, cudaStreamNonBlocking);
        cudaEventCreateWithFlags(&evF, cudaEventDisableTiming);
        cudaEventCreateWithFlags(&evJ, cudaEventDisableTiming);
        cudaFuncSetAttribute(mma_gemm128<float>,
                             cudaFuncAttributeMaxDynamicSharedMemorySize, SM_U32 * 4);
        cudaFuncSetAttribute(mma_gemm128<__half>,
                             cudaFuncAttributeMaxDynamicSharedMemorySize, SM_U32 * 4);
    }

    const int nb = (M + 255) / 256;           // 196
    const int gemmBlocks = (M + 127) / 128;   // 391
    const int spmmBlocks = (M + 7) / 8;
    const int nE4 = (nE + 3) / 4;

    // ---- Fork: CSR build on s2, weight pack + layer-1 GEMM on main ----
    cudaEventRecord(evF, 0);
    cudaStreamWaitEvent(s2, evF, 0);

    zero_int4<<<(M / 4 + 255) / 256, 256, 0, s2>>>((int4*)cnt, (M + 3) / 4);
    hist_dst4<<<((nE / 4) + 255) / 256, 256, 0, s2>>>((const int4*)edst, cnt, nE / 4);
    scan_p1<<<nb, 256, 0, s2>>>(cnt, tmp, bsum, M);
    scan_p3<<<nb, 256, 0, s2>>>(tmp, bsum, rp, cursor, M, nb, nE);
    scatter_edges4<<<(nE4 + 255) / 256, 256, 0, s2>>>(esrc, edst, ew, cursor, pe, nE);
    cudaEventRecord(evJ, s2);

    conv_weights<<<160, 256>>>(W1, Wh, W1h, W1l, Whh, Whl);
    mma_gemm128<float><<<gemmBlocks, 256, SM_U32 * 4>>>(x, W1h, W1l, Ah, M, NFEAT);

    cudaStreamWaitEvent(0, evJ, 0);   // join

    // Layer 1 aggregation (fp16 out)
    spmm_csr128h<<<spmmBlocks, 256>>>(Ah, rp, pe, b1, Bh, M);

    // Layer 2 (fp16 in)
    mma_gemm128<__half><<<gemmBlocks, 256, SM_U32 * 4>>>(Bh, Whh, Whl, Ah, M, NHID);
    spmm_csr128h<<<spmmBlocks, 256>>>(Ah, rp, pe, bh, Bh, M);

    // Layer 3 + log_softmax
    sgemm40<<<(M + 31) / 32, 256>>>(Bh, W2, Ch, M);
    spmm_csr40_lsm<<<spmmBlocks, 256>>>(Ch, rp, pe, b2, out, M);
}